// round 2
// baseline (speedup 1.0000x reference)
#include <cuda_runtime.h>
#include <math.h>

// ---------------------------------------------------------------------------
// Problem: WanSelfAttention  B=1, L=5000, dim=1536, heads=12, head_dim=128
//   q = rms_norm(x@Wq+bq, gq); k = rms_norm(x@Wk+bk, gk); v = x@Wv+bv
//   q,k = rope(q,k); o = softmax(q k^T / sqrt(d)) v; out = o@Wo + bo
// All fp32. Round-1 baseline: SIMT register-tiled GEMMs + flash attention.
// ---------------------------------------------------------------------------

#define MAX_L 5120
#define MAX_DIM 1536

// scratch (static device globals: no allocations allowed)
__device__ float g_Q[MAX_L * MAX_DIM];
__device__ float g_K[MAX_L * MAX_DIM];
__device__ float g_V[MAX_L * MAX_DIM];
__device__ float g_O[MAX_L * MAX_DIM];

// ---------------------------------------------------------------------------
// GEMM: C[M,N] = A[M,K] @ W[K,N] + bias[N]
// 64x64 block tile, BK=16, 256 threads, 4x4 register micro-tile.
// ---------------------------------------------------------------------------
__global__ void gemm_bias_kernel(const float* __restrict__ A,
                                 const float* __restrict__ W,
                                 const float* __restrict__ bias,
                                 float* __restrict__ C,
                                 int M, int N, int K)
{
    const int BM = 64, BN = 64, BK = 16;
    __shared__ float As[BM][BK + 1];   // +1 pad
    __shared__ float Bs[BK][BN];

    int tid = threadIdx.x;
    int ty = tid >> 4;        // 0..15
    int tx = tid & 15;        // 0..15
    int rowBase = blockIdx.x * BM;
    int colBase = blockIdx.y * BN;

    float acc[4][4];
#pragma unroll
    for (int i = 0; i < 4; i++)
#pragma unroll
        for (int j = 0; j < 4; j++) acc[i][j] = 0.f;

    // loader mapping
    int arow  = tid >> 2;            // 0..63
    int acol4 = (tid & 3) * 4;       // 0,4,8,12
    int brow  = tid >> 4;            // 0..15
    int bcol4 = (tid & 15) * 4;      // 0..60

    for (int kt = 0; kt < K; kt += BK) {
        float4 av = make_float4(0.f, 0.f, 0.f, 0.f);
        int gr = rowBase + arow;
        if (gr < M)
            av = *reinterpret_cast<const float4*>(&A[(size_t)gr * K + kt + acol4]);
        As[arow][acol4 + 0] = av.x;
        As[arow][acol4 + 1] = av.y;
        As[arow][acol4 + 2] = av.z;
        As[arow][acol4 + 3] = av.w;

        float4 bv = *reinterpret_cast<const float4*>(
            &W[(size_t)(kt + brow) * N + colBase + bcol4]);
        *reinterpret_cast<float4*>(&Bs[brow][bcol4]) = bv;

        __syncthreads();

#pragma unroll
        for (int kk = 0; kk < BK; kk++) {
            float a[4], b[4];
#pragma unroll
            for (int i = 0; i < 4; i++) a[i] = As[ty * 4 + i][kk];
#pragma unroll
            for (int j = 0; j < 4; j++) b[j] = Bs[kk][tx + 16 * j];
#pragma unroll
            for (int i = 0; i < 4; i++)
#pragma unroll
                for (int j = 0; j < 4; j++) acc[i][j] += a[i] * b[j];
        }
        __syncthreads();
    }

#pragma unroll
    for (int i = 0; i < 4; i++) {
        int r = rowBase + ty * 4 + i;
        if (r < M) {
#pragma unroll
            for (int j = 0; j < 4; j++) {
                int ccol = colBase + tx + 16 * j;
                C[(size_t)r * N + ccol] = acc[i][j] + bias[ccol];
            }
        }
    }
}

// ---------------------------------------------------------------------------
// Fused RMSNorm (over full dim) + RoPE (per head pair) in-place.
// One block per token. blockDim = dim/4 (each thread owns 4 contiguous
// elements = 2 rope pairs).
// ---------------------------------------------------------------------------
__global__ void rms_rope_kernel(float* __restrict__ Y,
                                const float* __restrict__ g,
                                const float* __restrict__ freqs,
                                const int* __restrict__ grid_sizes,
                                int L, int dim, int c)
{
    int t = blockIdx.x;
    int tid = threadIdx.x;
    float* row = Y + (size_t)t * dim;

    float4 v = *reinterpret_cast<const float4*>(&row[4 * tid]);
    float ss = v.x * v.x + v.y * v.y + v.z * v.z + v.w * v.w;

    __shared__ float red[32];
#pragma unroll
    for (int o = 16; o > 0; o >>= 1) ss += __shfl_xor_sync(0xffffffffu, ss, o);
    int warp = tid >> 5, lane = tid & 31;
    int nwarps = blockDim.x >> 5;
    if (lane == 0) red[warp] = ss;
    __syncthreads();
    __shared__ float s_inv;
    if (tid == 0) {
        float tot = 0.f;
        for (int i = 0; i < nwarps; i++) tot += red[i];
        s_inv = rsqrtf(tot / (float)dim + 1e-6f);
    }
    __syncthreads();
    float inv = s_inv;

    float4 gg = *reinterpret_cast<const float4*>(&g[4 * tid]);
    v.x *= inv * gg.x;
    v.y *= inv * gg.y;
    v.z *= inv * gg.z;
    v.w *= inv * gg.w;

    // RoPE
    int gf = grid_sizes[0], gh = grid_sizes[1], gw = grid_sizes[2];
    int hw = gh * gw;
    int sl = gf * hw;
    if (t < sl) {
        int fi = t / hw;
        int rem = t - fi * hw;
        int hi = rem / gw;
        int wi = rem - hi * gw;
        int c1 = c / 3;
        int c0 = c - 2 * c1;

        // pair indices within the token: p0 = 2*tid, p1 = 2*tid+1
#pragma unroll
        for (int pp = 0; pp < 2; pp++) {
            int p = 2 * tid + pp;
            int j = p % c;
            int idx = (j < c0) ? fi : ((j < c0 + c1) ? hi : wi);
            float ang = freqs[(size_t)idx * c + j];
            float sn, cs;
            sincosf(ang, &sn, &cs);
            float re = (pp == 0) ? v.x : v.z;
            float im = (pp == 0) ? v.y : v.w;
            float re2 = re * cs - im * sn;
            float im2 = re * sn + im * cs;
            if (pp == 0) { v.x = re2; v.y = im2; }
            else         { v.z = re2; v.w = im2; }
        }
    }
    *reinterpret_cast<float4*>(&row[4 * tid]) = v;
}

// ---------------------------------------------------------------------------
// Flash attention, fp32. 64 queries x 64 keys per tile, d=128 fixed.
// 256 threads; S micro-tile 4x4, O micro-tile 4x8.
// ---------------------------------------------------------------------------
__global__ void attn_kernel(const float* __restrict__ Q,
                            const float* __restrict__ K,
                            const float* __restrict__ V,
                            float* __restrict__ O,
                            const int* __restrict__ seq_lens,
                            int L, int nheads)
{
    const int AQ = 64, AK = 64, AD = 128;
    const int QS = 129, KSs = 129, VSs = 128;

    extern __shared__ float sm[];
    float* Qs  = sm;                       // AQ*QS
    float* Ks  = Qs + AQ * QS;             // AK*KSs
    float* Vs  = Ks + AK * KSs;            // AK*VSs
    float* Ss  = Vs + AK * VSs;            // AQ*AK
    float* s_m = Ss + AQ * AK;             // AQ
    float* s_l = s_m + AQ;                 // AQ
    float* s_c = s_l + AQ;                 // AQ

    int h  = blockIdx.y;
    int q0 = blockIdx.x * AQ;
    int tid = threadIdx.x;
    int ty = tid >> 4, tx = tid & 15;
    int seqlen = seq_lens[0];
    if (seqlen > L) seqlen = L;
    const float scale = rsqrtf((float)AD);
    const size_t rowStride = (size_t)nheads * AD;

    // load Q tile (scaled)
    for (int idx = tid; idx < AQ * AD; idx += 256) {
        int r = idx >> 7, dcol = idx & 127;
        int gr = q0 + r;
        float val = 0.f;
        if (gr < L) val = Q[(size_t)gr * rowStride + (size_t)h * AD + dcol] * scale;
        Qs[r * QS + dcol] = val;
    }
    if (tid < AQ) { s_m[tid] = -INFINITY; s_l[tid] = 0.f; }

    float acc[4][8];
#pragma unroll
    for (int i = 0; i < 4; i++)
#pragma unroll
        for (int j = 0; j < 8; j++) acc[i][j] = 0.f;
    __syncthreads();

    int nkt = (seqlen + AK - 1) / AK;
    for (int kt = 0; kt < nkt; kt++) {
        int k0 = kt * AK;
        // load K and V tiles
        for (int idx = tid; idx < AK * (AD / 4); idx += 256) {
            int r  = idx >> 5;            // 0..63
            int c4 = (idx & 31) * 4;      // 0..124
            int gr = k0 + r;
            float4 kv = make_float4(0.f, 0.f, 0.f, 0.f);
            float4 vv = make_float4(0.f, 0.f, 0.f, 0.f);
            if (gr < seqlen) {
                kv = *reinterpret_cast<const float4*>(&K[(size_t)gr * rowStride + (size_t)h * AD + c4]);
                vv = *reinterpret_cast<const float4*>(&V[(size_t)gr * rowStride + (size_t)h * AD + c4]);
            }
            Ks[r * KSs + c4 + 0] = kv.x;
            Ks[r * KSs + c4 + 1] = kv.y;
            Ks[r * KSs + c4 + 2] = kv.z;
            Ks[r * KSs + c4 + 3] = kv.w;
            *reinterpret_cast<float4*>(&Vs[r * VSs + c4]) = vv;
        }
        __syncthreads();

        // S = Q K^T  (4x4 micro-tile, cols tx+16j)
        float s[4][4];
#pragma unroll
        for (int i = 0; i < 4; i++)
#pragma unroll
            for (int j = 0; j < 4; j++) s[i][j] = 0.f;

        for (int dd = 0; dd < AD; dd++) {
            float qf[4], kf[4];
#pragma unroll
            for (int i = 0; i < 4; i++) qf[i] = Qs[(ty * 4 + i) * QS + dd];
#pragma unroll
            for (int j = 0; j < 4; j++) kf[j] = Ks[(tx + 16 * j) * KSs + dd];
#pragma unroll
            for (int i = 0; i < 4; i++)
#pragma unroll
                for (int j = 0; j < 4; j++) s[i][j] += qf[i] * kf[j];
        }
#pragma unroll
        for (int i = 0; i < 4; i++)
#pragma unroll
            for (int j = 0; j < 4; j++) {
                int col = tx + 16 * j;
                float val = (k0 + col < seqlen) ? s[i][j] : -1e30f;
                Ss[(ty * 4 + i) * AK + col] = val;
            }
        __syncthreads();

        // online softmax bookkeeping (one thread per row)
        if (tid < AQ) {
            float mold = s_m[tid];
            float mnew = mold;
            float* srow = Ss + tid * AK;
#pragma unroll 8
            for (int cI = 0; cI < AK; cI++) mnew = fmaxf(mnew, srow[cI]);
            float cf = __expf(mold - mnew);
            float ls = 0.f;
#pragma unroll 8
            for (int cI = 0; cI < AK; cI++) {
                float p = __expf(srow[cI] - mnew);
                srow[cI] = p;
                ls += p;
            }
            s_m[tid] = mnew;
            s_l[tid] = s_l[tid] * cf + ls;
            s_c[tid] = cf;
        }
        __syncthreads();

        // O = O*corr + P @ V   (4x8 micro-tile, cols tx+16j)
#pragma unroll
        for (int i = 0; i < 4; i++) {
            float cf = s_c[ty * 4 + i];
#pragma unroll
            for (int j = 0; j < 8; j++) acc[i][j] *= cf;
        }
        for (int kk = 0; kk < AK; kk++) {
            float pf[4], vf[8];
#pragma unroll
            for (int i = 0; i < 4; i++) pf[i] = Ss[(ty * 4 + i) * AK + kk];
#pragma unroll
            for (int j = 0; j < 8; j++) vf[j] = Vs[kk * VSs + tx + 16 * j];
#pragma unroll
            for (int i = 0; i < 4; i++)
#pragma unroll
                for (int j = 0; j < 8; j++) acc[i][j] += pf[i] * vf[j];
        }
        __syncthreads();
    }

    // final normalize + store
#pragma unroll
    for (int i = 0; i < 4; i++) {
        int gr = q0 + ty * 4 + i;
        if (gr < L) {
            float invl = 1.f / s_l[ty * 4 + i];
#pragma unroll
            for (int j = 0; j < 8; j++) {
                int col = tx + 16 * j;
                O[(size_t)gr * rowStride + (size_t)h * AD + col] = acc[i][j] * invl;
            }
        }
    }
}

// ---------------------------------------------------------------------------
// Host launcher
// ---------------------------------------------------------------------------
extern "C" void kernel_launch(void* const* d_in, const int* in_sizes, int n_in,
                              void* d_out, int out_size)
{
    const float* x        = (const float*)d_in[0];
    const int*   seq_lens = (const int*)  d_in[1];
    const int*   grid_szs = (const int*)  d_in[2];
    const float* freqs    = (const float*)d_in[3];
    const float* Wq       = (const float*)d_in[4];
    const float* bq       = (const float*)d_in[5];
    const float* Wk       = (const float*)d_in[6];
    const float* bk       = (const float*)d_in[7];
    const float* Wv       = (const float*)d_in[8];
    const float* bv       = (const float*)d_in[9];
    const float* Wo       = (const float*)d_in[10];
    const float* bo       = (const float*)d_in[11];
    const float* gq       = (const float*)d_in[12];
    const float* gk       = (const float*)d_in[13];

    int dim = in_sizes[5];            // 1536 (bq)
    int L   = in_sizes[0] / dim;      // 5000
    int c   = in_sizes[3] / 1024;     // 64  (freqs is [1024, c])
    int dh  = 2 * c;                  // 128
    int n   = dim / dh;               // 12

    float *Qb, *Kb, *Vb, *Ob;
    cudaGetSymbolAddress((void**)&Qb, g_Q);
    cudaGetSymbolAddress((void**)&Kb, g_K);
    cudaGetSymbolAddress((void**)&Vb, g_V);
    cudaGetSymbolAddress((void**)&Ob, g_O);

    dim3 ggrid((L + 63) / 64, dim / 64);

    gemm_bias_kernel<<<ggrid, 256>>>(x, Wq, bq, Qb, L, dim, dim);
    gemm_bias_kernel<<<ggrid, 256>>>(x, Wk, bk, Kb, L, dim, dim);
    gemm_bias_kernel<<<ggrid, 256>>>(x, Wv, bv, Vb, L, dim, dim);

    rms_rope_kernel<<<L, dim / 4>>>(Qb, gq, freqs, grid_szs, L, dim, c);
    rms_rope_kernel<<<L, dim / 4>>>(Kb, gk, freqs, grid_szs, L, dim, c);

    size_t smem = (size_t)(64 * 129 + 64 * 129 + 64 * 128 + 64 * 64 + 3 * 64) * sizeof(float);
    cudaFuncSetAttribute(attn_kernel, cudaFuncAttributeMaxDynamicSharedMemorySize, (int)smem);
    attn_kernel<<<dim3((L + 63) / 64, n), 256, smem>>>(Qb, Kb, Vb, Ob, seq_lens, L, n);

    gemm_bias_kernel<<<ggrid, 256>>>(Ob, Wo, bo, (float*)d_out, L, dim, dim);
}

// round 6
// speedup vs baseline: 2.9907x; 2.9907x over previous
#include <cuda_runtime.h>
#include <math.h>
#include <stdint.h>

// ---------------------------------------------------------------------------
// WanSelfAttention: B=1, L=5000, dim=1536, heads=12, head_dim=128, fp32 I/O.
// R5: all matmuls on tensor cores via 3xTF32 (error-compensated split:
// C += Ah*Bh + Ah*Bl + Al*Bh) -> fp32-quality results at tensor-core speed.
// cp.async double-buffered smem pipelines.
// ---------------------------------------------------------------------------

#define MAX_L 5120
#define MAX_DIM 1536

__device__ float g_Q[MAX_L * MAX_DIM];
__device__ float g_K[MAX_L * MAX_DIM];
__device__ float g_V[MAX_L * MAX_DIM];
__device__ float g_O[MAX_L * MAX_DIM];

// ---------------- helpers ----------------
__device__ __forceinline__ void cp16(void* smem_dst, const void* gsrc) {
    uint32_t s = (uint32_t)__cvta_generic_to_shared(smem_dst);
    asm volatile("cp.async.cg.shared.global [%0], [%1], 16;\n" :: "r"(s), "l"(gsrc));
}
#define CP_COMMIT() asm volatile("cp.async.commit_group;\n" ::: "memory")
#define CP_WAIT(n)  asm volatile("cp.async.wait_group %0;\n" :: "n"(n) : "memory")

__device__ __forceinline__ void mma_tf32(float* c, const uint32_t* a, const uint32_t* b) {
    asm volatile(
        "mma.sync.aligned.m16n8k8.row.col.f32.tf32.tf32.f32 "
        "{%0,%1,%2,%3}, {%4,%5,%6,%7}, {%8,%9}, {%0,%1,%2,%3};\n"
        : "+f"(c[0]), "+f"(c[1]), "+f"(c[2]), "+f"(c[3])
        : "r"(a[0]), "r"(a[1]), "r"(a[2]), "r"(a[3]), "r"(b[0]), "r"(b[1]));
}

// split fp32 -> (tf32 hi, tf32 lo) such that hi + lo ~= x to ~22 bits
__device__ __forceinline__ void split_tf32(float x, uint32_t& hi, uint32_t& lo) {
    uint32_t h;
    asm("cvt.rna.tf32.f32 %0, %1;" : "=r"(h) : "f"(x));
    float l = x - __uint_as_float(h);
    uint32_t lr;
    asm("cvt.rna.tf32.f32 %0, %1;" : "=r"(lr) : "f"(l));
    hi = h; lo = lr;
}

// 3xTF32 mma: c += Al*Bh + Ah*Bl + Ah*Bh
__device__ __forceinline__ void mma3(float* c,
                                     const uint32_t* ah, const uint32_t* al,
                                     const uint32_t* bh, const uint32_t* bl) {
    mma_tf32(c, al, bh);
    mma_tf32(c, ah, bl);
    mma_tf32(c, ah, bh);
}

// ---------------------------------------------------------------------------
// GEMM: C[M,N] = A[M,K] @ W[K,N] + bias.  BM=128 BN=128 BK=32, 256 thr.
// Warps 2(m) x 4(n): warp tile 64x32 -> 4x4 m16n8 mma tiles, 3xTF32.
// ---------------------------------------------------------------------------
__global__ void gemm_tf32_kernel(const float* __restrict__ A,
                                 const float* __restrict__ W,
                                 const float* __restrict__ bias,
                                 float* __restrict__ C,
                                 int M, int N, int K)
{
    const int BM = 128, BN = 128, BK = 32;
    const int AS = 36, BS = 132;
    extern __shared__ float sh[];
    float* As = sh;                  // 2 * 128 * 36
    float* Bs = sh + 2 * BM * AS;    // 2 * 32 * 132

    int tid = threadIdx.x;
    int lane = tid & 31, warp = tid >> 5;
    int wm = warp >> 2, wn = warp & 3;
    int g = lane >> 2, tg = lane & 3;
    int row0 = blockIdx.x * BM, col0 = blockIdx.y * BN;

    float acc[4][4][4];
#pragma unroll
    for (int mt = 0; mt < 4; mt++)
#pragma unroll
        for (int nt = 0; nt < 4; nt++)
#pragma unroll
            for (int r = 0; r < 4; r++) acc[mt][nt][r] = 0.f;

    auto issue = [&](int kt, int buf) {
        float* Ad = As + buf * BM * AS;
        float* Bd = Bs + buf * BK * BS;
#pragma unroll
        for (int i = 0; i < 4; i++) {
            int idx = tid + i * 256;
            int r = idx >> 3, c4 = (idx & 7) << 2;
            int gr = row0 + r; if (gr >= M) gr = M - 1;
            cp16(Ad + r * AS + c4, A + (size_t)gr * K + kt + c4);
        }
#pragma unroll
        for (int i = 0; i < 4; i++) {
            int idx = tid + i * 256;
            int r = idx >> 5, c4 = (idx & 31) << 2;
            cp16(Bd + r * BS + c4, W + (size_t)(kt + r) * N + col0 + c4);
        }
    };

    issue(0, 0); CP_COMMIT();
    int nk = K / BK;
    for (int t = 0; t < nk; t++) {
        int buf = t & 1;
        if (t + 1 < nk) { issue((t + 1) * BK, buf ^ 1); CP_COMMIT(); CP_WAIT(1); }
        else           { CP_WAIT(0); }
        __syncthreads();

        const float* Ab = As + buf * BM * AS + (wm * 64) * AS;
        const float* Bb = Bs + buf * BK * BS + wn * 32;
#pragma unroll
        for (int ks = 0; ks < 4; ks++) {
            int kb = ks * 8;
            uint32_t ah[4][4], al[4][4], bh[4][2], bl[4][2];
#pragma unroll
            for (int mt = 0; mt < 4; mt++) {
                const float* ap = Ab + mt * 16 * AS + kb;
                split_tf32(ap[g * AS + tg],            ah[mt][0], al[mt][0]);
                split_tf32(ap[(g + 8) * AS + tg],      ah[mt][1], al[mt][1]);
                split_tf32(ap[g * AS + tg + 4],        ah[mt][2], al[mt][2]);
                split_tf32(ap[(g + 8) * AS + tg + 4],  ah[mt][3], al[mt][3]);
            }
#pragma unroll
            for (int nt = 0; nt < 4; nt++) {
                const float* bp = Bb + kb * BS + nt * 8;
                split_tf32(bp[tg * BS + g],        bh[nt][0], bl[nt][0]);
                split_tf32(bp[(tg + 4) * BS + g],  bh[nt][1], bl[nt][1]);
            }
#pragma unroll
            for (int mt = 0; mt < 4; mt++)
#pragma unroll
                for (int nt = 0; nt < 4; nt++)
                    mma3(acc[mt][nt], ah[mt], al[mt], bh[nt], bl[nt]);
        }
        __syncthreads();
    }

#pragma unroll
    for (int mt = 0; mt < 4; mt++) {
#pragma unroll
        for (int nt = 0; nt < 4; nt++) {
            int col = col0 + wn * 32 + nt * 8 + 2 * tg;
            float2 b2 = *(const float2*)&bias[col];
            int r0 = row0 + wm * 64 + mt * 16 + g;
            if (r0 < M) {
                float2 o = { acc[mt][nt][0] + b2.x, acc[mt][nt][1] + b2.y };
                *(float2*)&C[(size_t)r0 * N + col] = o;
            }
            int r1 = r0 + 8;
            if (r1 < M) {
                float2 o = { acc[mt][nt][2] + b2.x, acc[mt][nt][3] + b2.y };
                *(float2*)&C[(size_t)r1 * N + col] = o;
            }
        }
    }
}

// ---------------------------------------------------------------------------
// Fused RMSNorm + RoPE (in-place, one block per token)
// ---------------------------------------------------------------------------
__global__ void rms_rope_kernel(float* __restrict__ Y,
                                const float* __restrict__ g,
                                const float* __restrict__ freqs,
                                const int* __restrict__ grid_sizes,
                                int L, int dim, int c)
{
    int t = blockIdx.x;
    int tid = threadIdx.x;
    float* row = Y + (size_t)t * dim;

    float4 v = *reinterpret_cast<const float4*>(&row[4 * tid]);
    float ss = v.x * v.x + v.y * v.y + v.z * v.z + v.w * v.w;

    __shared__ float red[32];
#pragma unroll
    for (int o = 16; o > 0; o >>= 1) ss += __shfl_xor_sync(0xffffffffu, ss, o);
    int warp = tid >> 5, lane = tid & 31;
    int nwarps = blockDim.x >> 5;
    if (lane == 0) red[warp] = ss;
    __syncthreads();
    __shared__ float s_inv;
    if (tid == 0) {
        float tot = 0.f;
        for (int i = 0; i < nwarps; i++) tot += red[i];
        s_inv = rsqrtf(tot / (float)dim + 1e-6f);
    }
    __syncthreads();
    float inv = s_inv;

    float4 gg = *reinterpret_cast<const float4*>(&g[4 * tid]);
    v.x *= inv * gg.x; v.y *= inv * gg.y; v.z *= inv * gg.z; v.w *= inv * gg.w;

    int gf = grid_sizes[0], gh = grid_sizes[1], gw = grid_sizes[2];
    int hw = gh * gw;
    int sl = gf * hw;
    if (t < sl) {
        int fi = t / hw;
        int rem = t - fi * hw;
        int hi = rem / gw;
        int wi = rem - hi * gw;
        int c1 = c / 3;
        int c0 = c - 2 * c1;
#pragma unroll
        for (int pp = 0; pp < 2; pp++) {
            int p = 2 * tid + pp;
            int j = p % c;
            int idx = (j < c0) ? fi : ((j < c0 + c1) ? hi : wi);
            float ang = freqs[(size_t)idx * c + j];
            float sn, cs;
            sincosf(ang, &sn, &cs);
            float re = (pp == 0) ? v.x : v.z;
            float im = (pp == 0) ? v.y : v.w;
            float re2 = re * cs - im * sn;
            float im2 = re * sn + im * cs;
            if (pp == 0) { v.x = re2; v.y = im2; }
            else         { v.z = re2; v.w = im2; }
        }
    }
    *reinterpret_cast<float4*>(&row[4 * tid]) = v;
}

// ---------------------------------------------------------------------------
// Flash attention on tensor cores (3xTF32). 64q x 64k tiles, d=128.
// 256 thr, warps 2x4. S: warp tile 32x16 (2x2 mma). PV: warp tile 32x32 (2x4).
// K/V double-buffered via cp.async. Scale folded into softmax.
// ---------------------------------------------------------------------------
__global__ void attn_tf32_kernel(const float* __restrict__ Q,
                                 const float* __restrict__ K,
                                 const float* __restrict__ V,
                                 float* __restrict__ O,
                                 const int* __restrict__ seq_lens,
                                 int L, int nheads)
{
    const int AQ = 64, AK = 64, AD = 128;
    const int QS = 132, SS = 68;
    extern __shared__ float sh[];
    float* Qs  = sh;                      // 64*132
    float* Ks  = Qs + AQ * QS;            // 2 * 64*132
    float* Vs  = Ks + 2 * AK * QS;        // 2 * 64*132
    float* Ps  = Vs + 2 * AK * QS;        // 64*68
    float* s_m = Ps + AQ * SS;            // 64
    float* s_l = s_m + AQ;                // 64
    float* s_c = s_l + AQ;                // 64

    int h  = blockIdx.y;
    int q0 = blockIdx.x * AQ;
    int tid = threadIdx.x, lane = tid & 31, warp = tid >> 5;
    int wm = warp >> 2, wn = warp & 3;
    int g = lane >> 2, tg = lane & 3;
    int seqlen = seq_lens[0]; if (seqlen > L) seqlen = L;
    const float scale = rsqrtf((float)AD);
    const size_t rstride = (size_t)nheads * AD;
    const float* Qh = Q + (size_t)h * AD;
    const float* Kh = K + (size_t)h * AD;
    const float* Vh = V + (size_t)h * AD;
    float* Oh = O + (size_t)h * AD;

    // Q tile (one-shot)
#pragma unroll
    for (int i = 0; i < 8; i++) {
        int idx = tid + i * 256;
        int r = idx >> 5, c4 = (idx & 31) << 2;
        int gr = q0 + r; if (gr >= L) gr = L - 1;
        cp16(Qs + r * QS + c4, Qh + (size_t)gr * rstride + c4);
    }
    auto issueKV = [&](int k0, int buf) {
        float* Kd = Ks + buf * AK * QS;
        float* Vd = Vs + buf * AK * QS;
#pragma unroll
        for (int i = 0; i < 8; i++) {
            int idx = tid + i * 256;
            int r = idx >> 5, c4 = (idx & 31) << 2;
            int gr = k0 + r; if (gr >= seqlen) gr = seqlen - 1;
            cp16(Kd + r * QS + c4, Kh + (size_t)gr * rstride + c4);
            cp16(Vd + r * QS + c4, Vh + (size_t)gr * rstride + c4);
        }
    };
    issueKV(0, 0); CP_COMMIT();

    if (tid < AQ) { s_m[tid] = -1e30f; s_l[tid] = 0.f; }

    float acc_o[2][4][4];
#pragma unroll
    for (int mt = 0; mt < 2; mt++)
#pragma unroll
        for (int nt = 0; nt < 4; nt++)
#pragma unroll
            for (int r = 0; r < 4; r++) acc_o[mt][nt][r] = 0.f;

    int nkt = (seqlen + AK - 1) / AK;
    for (int t = 0; t < nkt; t++) {
        int buf = t & 1;
        if (t + 1 < nkt) { issueKV((t + 1) * AK, buf ^ 1); CP_COMMIT(); CP_WAIT(1); }
        else            { CP_WAIT(0); }
        __syncthreads();

        // ---- S = Q K^T (3xTF32) ----
        const float* Kb = Ks + buf * AK * QS;
        float acc_s[2][2][4];
#pragma unroll
        for (int mt = 0; mt < 2; mt++)
#pragma unroll
            for (int nt = 0; nt < 2; nt++)
#pragma unroll
                for (int r = 0; r < 4; r++) acc_s[mt][nt][r] = 0.f;

#pragma unroll
        for (int ks = 0; ks < 16; ks++) {
            int kb = ks * 8;
            uint32_t ah[2][4], al[2][4], bh[2][2], bl[2][2];
#pragma unroll
            for (int mt = 0; mt < 2; mt++) {
                const float* ap = Qs + (wm * 32 + mt * 16) * QS + kb;
                split_tf32(ap[g * QS + tg],           ah[mt][0], al[mt][0]);
                split_tf32(ap[(g + 8) * QS + tg],     ah[mt][1], al[mt][1]);
                split_tf32(ap[g * QS + tg + 4],       ah[mt][2], al[mt][2]);
                split_tf32(ap[(g + 8) * QS + tg + 4], ah[mt][3], al[mt][3]);
            }
#pragma unroll
            for (int nt = 0; nt < 2; nt++) {
                const float* bp = Kb + (wn * 16 + nt * 8) * QS + kb;
                split_tf32(bp[g * QS + tg],     bh[nt][0], bl[nt][0]);
                split_tf32(bp[g * QS + tg + 4], bh[nt][1], bl[nt][1]);
            }
#pragma unroll
            for (int mt = 0; mt < 2; mt++)
#pragma unroll
                for (int nt = 0; nt < 2; nt++)
                    mma3(acc_s[mt][nt], ah[mt], al[mt], bh[nt], bl[nt]);
        }
        // write S
#pragma unroll
        for (int mt = 0; mt < 2; mt++) {
            int r0 = wm * 32 + mt * 16 + g;
#pragma unroll
            for (int nt = 0; nt < 2; nt++) {
                int cc = wn * 16 + nt * 8 + 2 * tg;
                Ps[r0 * SS + cc]           = acc_s[mt][nt][0];
                Ps[r0 * SS + cc + 1]       = acc_s[mt][nt][1];
                Ps[(r0 + 8) * SS + cc]     = acc_s[mt][nt][2];
                Ps[(r0 + 8) * SS + cc + 1] = acc_s[mt][nt][3];
            }
        }
        __syncthreads();

        // ---- online softmax: 4 threads per row ----
        {
            int row = tid >> 2, sub = tid & 3;
            int k0 = t * AK;
            float* pr = Ps + row * SS + sub * 16;
            float vals[16];
            float mx = -1e30f;
#pragma unroll
            for (int j = 0; j < 16; j++) {
                int col = sub * 16 + j;
                float vv = (k0 + col < seqlen) ? pr[j] * scale : -1e30f;
                vals[j] = vv;
                mx = fmaxf(mx, vv);
            }
            mx = fmaxf(mx, __shfl_xor_sync(0xffffffffu, mx, 1));
            mx = fmaxf(mx, __shfl_xor_sync(0xffffffffu, mx, 2));
            float mold = s_m[row];
            float mnew = fmaxf(mold, mx);
            float ls = 0.f;
#pragma unroll
            for (int j = 0; j < 16; j++) {
                float p = __expf(vals[j] - mnew);
                pr[j] = p;
                ls += p;
            }
            ls += __shfl_xor_sync(0xffffffffu, ls, 1);
            ls += __shfl_xor_sync(0xffffffffu, ls, 2);
            if (sub == 0) {
                float cf = __expf(mold - mnew);
                s_m[row] = mnew;
                s_l[row] = s_l[row] * cf + ls;
                s_c[row] = cf;
            }
        }
        __syncthreads();

        // ---- rescale + O += P @ V (3xTF32) ----
        const float* Vb = Vs + buf * AK * QS;
#pragma unroll
        for (int mt = 0; mt < 2; mt++) {
            int r0 = wm * 32 + mt * 16 + g;
            float cf0 = s_c[r0], cf1 = s_c[r0 + 8];
#pragma unroll
            for (int nt = 0; nt < 4; nt++) {
                acc_o[mt][nt][0] *= cf0; acc_o[mt][nt][1] *= cf0;
                acc_o[mt][nt][2] *= cf1; acc_o[mt][nt][3] *= cf1;
            }
        }
#pragma unroll
        for (int ks = 0; ks < 8; ks++) {
            int kb = ks * 8;
            uint32_t ah[2][4], al[2][4], bh[4][2], bl[4][2];
#pragma unroll
            for (int mt = 0; mt < 2; mt++) {
                const float* ap = Ps + (wm * 32 + mt * 16) * SS + kb;
                split_tf32(ap[g * SS + tg],           ah[mt][0], al[mt][0]);
                split_tf32(ap[(g + 8) * SS + tg],     ah[mt][1], al[mt][1]);
                split_tf32(ap[g * SS + tg + 4],       ah[mt][2], al[mt][2]);
                split_tf32(ap[(g + 8) * SS + tg + 4], ah[mt][3], al[mt][3]);
            }
#pragma unroll
            for (int nt = 0; nt < 4; nt++) {
                const float* bp = Vb + kb * QS + wn * 32 + nt * 8;
                split_tf32(bp[tg * QS + g],       bh[nt][0], bl[nt][0]);
                split_tf32(bp[(tg + 4) * QS + g], bh[nt][1], bl[nt][1]);
            }
#pragma unroll
            for (int mt = 0; mt < 2; mt++)
#pragma unroll
                for (int nt = 0; nt < 4; nt++)
                    mma3(acc_o[mt][nt], ah[mt], al[mt], bh[nt], bl[nt]);
        }
        __syncthreads();
    }

    // ---- epilogue: normalize + store ----
#pragma unroll
    for (int mt = 0; mt < 2; mt++) {
        int r0 = wm * 32 + mt * 16 + g;
        float il0 = 1.f / s_l[r0];
        float il1 = 1.f / s_l[r0 + 8];
#pragma unroll
        for (int nt = 0; nt < 4; nt++) {
            int cc = wn * 32 + nt * 8 + 2 * tg;
            int gr0 = q0 + r0;
            if (gr0 < L) {
                float2 o = { acc_o[mt][nt][0] * il0, acc_o[mt][nt][1] * il0 };
                *(float2*)&Oh[(size_t)gr0 * rstride + cc] = o;
            }
            int gr1 = gr0 + 8;
            if (gr1 < L) {
                float2 o = { acc_o[mt][nt][2] * il1, acc_o[mt][nt][3] * il1 };
                *(float2*)&Oh[(size_t)gr1 * rstride + cc] = o;
            }
        }
    }
}

// ---------------------------------------------------------------------------
// Host launcher
// ---------------------------------------------------------------------------
extern "C" void kernel_launch(void* const* d_in, const int* in_sizes, int n_in,
                              void* d_out, int out_size)
{
    const float* x        = (const float*)d_in[0];
    const int*   seq_lens = (const int*)  d_in[1];
    const int*   grid_szs = (const int*)  d_in[2];
    const float* freqs    = (const float*)d_in[3];
    const float* Wq       = (const float*)d_in[4];
    const float* bq       = (const float*)d_in[5];
    const float* Wk       = (const float*)d_in[6];
    const float* bk       = (const float*)d_in[7];
    const float* Wv       = (const float*)d_in[8];
    const float* bv       = (const float*)d_in[9];
    const float* Wo       = (const float*)d_in[10];
    const float* bo       = (const float*)d_in[11];
    const float* gq       = (const float*)d_in[12];
    const float* gk       = (const float*)d_in[13];

    int dim = in_sizes[5];            // 1536
    int L   = in_sizes[0] / dim;      // 5000
    int c   = in_sizes[3] / 1024;     // 64
    int dh  = 2 * c;                  // 128
    int n   = dim / dh;               // 12

    float *Qb, *Kb, *Vb, *Ob;
    cudaGetSymbolAddress((void**)&Qb, g_Q);
    cudaGetSymbolAddress((void**)&Kb, g_K);
    cudaGetSymbolAddress((void**)&Vb, g_V);
    cudaGetSymbolAddress((void**)&Ob, g_O);

    size_t gsmem = (size_t)(2 * 128 * 36 + 2 * 32 * 132) * sizeof(float);     // 70656
    size_t asmem = (size_t)(64 * 132 * 5 + 64 * 68 + 3 * 64) * sizeof(float); // 187136
    cudaFuncSetAttribute(gemm_tf32_kernel, cudaFuncAttributeMaxDynamicSharedMemorySize, (int)gsmem);
    cudaFuncSetAttribute(attn_tf32_kernel, cudaFuncAttributeMaxDynamicSharedMemorySize, (int)asmem);

    dim3 ggrid((L + 127) / 128, dim / 128);

    gemm_tf32_kernel<<<ggrid, 256, gsmem>>>(x, Wq, bq, Qb, L, dim, dim);
    gemm_tf32_kernel<<<ggrid, 256, gsmem>>>(x, Wk, bk, Kb, L, dim, dim);
    gemm_tf32_kernel<<<ggrid, 256, gsmem>>>(x, Wv, bv, Vb, L, dim, dim);

    rms_rope_kernel<<<L, dim / 4>>>(Qb, gq, freqs, grid_szs, L, dim, c);
    rms_rope_kernel<<<L, dim / 4>>>(Kb, gk, freqs, grid_szs, L, dim, c);

    attn_tf32_kernel<<<dim3((L + 63) / 64, n), 256, asmem>>>(Qb, Kb, Vb, Ob, seq_lens, L, n);

    gemm_tf32_kernel<<<ggrid, 256, gsmem>>>(Ob, Wo, bo, (float*)d_out, L, dim, dim);
}

// round 7
// speedup vs baseline: 5.8863x; 1.9682x over previous
#include <cuda_runtime.h>
#include <cuda_fp16.h>
#include <math.h>
#include <stdint.h>

// ---------------------------------------------------------------------------
// WanSelfAttention: B=1, L=5000, dim=1536, heads=12, head_dim=128, fp32 I/O.
// R6: fp16x3 error-compensated tensor cores (hi/lo split, C += Al*Bh + Ah*Bl
// + Ah*Bh). All operands pre-split & pair-packed in global memory so hot
// loops contain only LDS + MMA. Weights scaled x256 to avoid fp16 subnormal
// lo terms; descaled in GEMM epilogue.
// ---------------------------------------------------------------------------

#define MAX_L 5120
#define DIMV  1536
#define NPAIR 768            // DIMV/2

// fp32 intermediates
__device__ float g_Q[MAX_L * DIMV];
__device__ float g_K[MAX_L * DIMV];
__device__ float g_V[MAX_L * DIMV];
// packed fp16 hi/lo pair buffers
__device__ uint32_t g_Xp[2][MAX_L * NPAIR];
__device__ uint32_t g_Wp[8][NPAIR * DIMV];          // 4 weights x (hi,lo)
__device__ uint32_t g_Qp[2][MAX_L * NPAIR];
__device__ uint32_t g_Kp[2][MAX_L * NPAIR];
__device__ uint32_t g_Vp[2][(MAX_L / 2) * DIMV];    // pairs along token
__device__ uint32_t g_Op[2][MAX_L * NPAIR];

// ---------------- helpers ----------------
__device__ __forceinline__ void cp16(void* smem_dst, const void* gsrc) {
    uint32_t s = (uint32_t)__cvta_generic_to_shared(smem_dst);
    asm volatile("cp.async.cg.shared.global [%0], [%1], 16;\n" :: "r"(s), "l"(gsrc));
}
#define CP_COMMIT() asm volatile("cp.async.commit_group;\n" ::: "memory")
#define CP_WAIT(n)  asm volatile("cp.async.wait_group %0;\n" :: "n"(n) : "memory")

// split a pair (x,y) into packed fp16 hi and lo words (x in low half)
__device__ __forceinline__ void split2(float x, float y, uint32_t& hi, uint32_t& lo) {
    __half2 h = __floats2half2_rn(x, y);
    float2 hf = __half22float2(h);
    __half2 l = __floats2half2_rn(x - hf.x, y - hf.y);
    hi = *reinterpret_cast<uint32_t*>(&h);
    lo = *reinterpret_cast<uint32_t*>(&l);
}

__device__ __forceinline__ void mma_f16(float* c, const uint32_t* a, const uint32_t* b) {
    asm volatile(
        "mma.sync.aligned.m16n8k16.row.col.f32.f16.f16.f32 "
        "{%0,%1,%2,%3}, {%4,%5,%6,%7}, {%8,%9}, {%0,%1,%2,%3};\n"
        : "+f"(c[0]), "+f"(c[1]), "+f"(c[2]), "+f"(c[3])
        : "r"(a[0]), "r"(a[1]), "r"(a[2]), "r"(a[3]), "r"(b[0]), "r"(b[1]));
}
__device__ __forceinline__ void mma3(float* c,
                                     const uint32_t* ah, const uint32_t* al,
                                     const uint32_t* bh, const uint32_t* bl) {
    mma_f16(c, al, bh);
    mma_f16(c, ah, bl);
    mma_f16(c, ah, bh);
}

// ---------------------------------------------------------------------------
// Prep: split fp32 rows into packed pairs along the row (k = columns)
// ---------------------------------------------------------------------------
__global__ void split_rows_kernel(const float* __restrict__ X,
                                  uint32_t* __restrict__ hi, uint32_t* __restrict__ lo,
                                  int npairs)
{
    int i = blockIdx.x * 256 + threadIdx.x;
    if (i >= npairs) return;
    float2 v = reinterpret_cast<const float2*>(X)[i];
    uint32_t h, l; split2(v.x, v.y, h, l);
    hi[i] = h; lo[i] = l;
}

// Prep: split pairing along ROWS: out[r][c] = pack(W[2r][c], W[2r+1][c]) * scale
__global__ void split_k_kernel(const float* __restrict__ W,
                               uint32_t* __restrict__ hi, uint32_t* __restrict__ lo,
                               int Krows, int N, float scale)
{
    int i = blockIdx.x * 256 + threadIdx.x;
    int prows = (Krows + 1) / 2;
    if (i >= prows * N) return;
    int r = i / N, c0 = i - r * N;
    float x = W[(size_t)(2 * r) * N + c0] * scale;
    float y = (2 * r + 1 < Krows) ? W[(size_t)(2 * r + 1) * N + c0] * scale : 0.f;
    uint32_t h, l; split2(x, y, h, l);
    hi[i] = h; lo[i] = l;
}

// ---------------------------------------------------------------------------
// GEMM fp16x3: C[M,N] = (Ap @ Bp) * outScale + bias
// Ap: [M][Kp] packed pairs along k.  Bp: [Kp][N] packed pairs along k.
// BM=128 BN=128 BKP=16 pairs (K=32), 256 thr, warps 2x4, warp tile 64x32.
// ---------------------------------------------------------------------------
#define G_PA 20     // A smem pair stride
#define G_PB 136    // B smem pair stride
__global__ void __launch_bounds__(256)
gemm_f16x3_kernel(const uint32_t* __restrict__ Ahi, const uint32_t* __restrict__ Alo,
                  const uint32_t* __restrict__ Bhi, const uint32_t* __restrict__ Blo,
                  const float* __restrict__ bias, float* __restrict__ C,
                  int M, int N, int Kp, float outScale)
{
    const int ABUF = 128 * G_PA;     // 2560
    const int BBUF = 16 * G_PB;      // 2176
    extern __shared__ uint32_t sh[];
    uint32_t* Ah = sh;                     // 2*ABUF
    uint32_t* Al = Ah + 2 * ABUF;
    uint32_t* Bh = Al + 2 * ABUF;          // 2*BBUF
    uint32_t* Bl = Bh + 2 * BBUF;

    int tid = threadIdx.x;
    int lane = tid & 31, warp = tid >> 5;
    int wm = warp >> 2, wn = warp & 3;
    int g = lane >> 2, tg = lane & 3;
    int row0 = blockIdx.x * 128, col0 = blockIdx.y * 128;

    float acc[4][4][4];
#pragma unroll
    for (int mt = 0; mt < 4; mt++)
#pragma unroll
        for (int nt = 0; nt < 4; nt++)
#pragma unroll
            for (int r = 0; r < 4; r++) acc[mt][nt][r] = 0.f;

    auto issue = [&](int ktp, int buf) {
#pragma unroll
        for (int i = 0; i < 2; i++) {          // A: 512 chunks per array
            int idx = tid + i * 256;
            int r = idx >> 2, pc = (idx & 3) << 2;
            int gr = row0 + r; if (gr >= M) gr = M - 1;
            size_t go = (size_t)gr * Kp + ktp + pc;
            cp16(Ah + buf * ABUF + r * G_PA + pc, Ahi + go);
            cp16(Al + buf * ABUF + r * G_PA + pc, Alo + go);
        }
#pragma unroll
        for (int i = 0; i < 2; i++) {          // B: 512 chunks per array
            int idx = tid + i * 256;
            int r = idx >> 5, pc = (idx & 31) << 2;
            size_t go = (size_t)(ktp + r) * N + col0 + pc;
            cp16(Bh + buf * BBUF + r * G_PB + pc, Bhi + go);
            cp16(Bl + buf * BBUF + r * G_PB + pc, Blo + go);
        }
    };

    issue(0, 0); CP_COMMIT();
    int nk = Kp / 16;
    for (int t = 0; t < nk; t++) {
        int buf = t & 1;
        if (t + 1 < nk) { issue((t + 1) * 16, buf ^ 1); CP_COMMIT(); CP_WAIT(1); }
        else           { CP_WAIT(0); }
        __syncthreads();

        const uint32_t* Abh = Ah + buf * ABUF + (wm * 64) * G_PA;
        const uint32_t* Abl = Al + buf * ABUF + (wm * 64) * G_PA;
        const uint32_t* Bbh = Bh + buf * BBUF + wn * 32;
        const uint32_t* Bbl = Bl + buf * BBUF + wn * 32;
#pragma unroll
        for (int ks = 0; ks < 2; ks++) {
            int pb = ks * 8;
            uint32_t ah[4][4], al[4][4], bh[4][2], bl[4][2];
#pragma unroll
            for (int mt = 0; mt < 4; mt++) {
                int r0 = (mt * 16 + g) * G_PA, r1 = (mt * 16 + g + 8) * G_PA;
                ah[mt][0] = Abh[r0 + pb + tg];     al[mt][0] = Abl[r0 + pb + tg];
                ah[mt][1] = Abh[r1 + pb + tg];     al[mt][1] = Abl[r1 + pb + tg];
                ah[mt][2] = Abh[r0 + pb + tg + 4]; al[mt][2] = Abl[r0 + pb + tg + 4];
                ah[mt][3] = Abh[r1 + pb + tg + 4]; al[mt][3] = Abl[r1 + pb + tg + 4];
            }
#pragma unroll
            for (int nt = 0; nt < 4; nt++) {
                int cc = nt * 8 + g;
                bh[nt][0] = Bbh[(pb + tg) * G_PB + cc];     bl[nt][0] = Bbl[(pb + tg) * G_PB + cc];
                bh[nt][1] = Bbh[(pb + tg + 4) * G_PB + cc]; bl[nt][1] = Bbl[(pb + tg + 4) * G_PB + cc];
            }
#pragma unroll
            for (int mt = 0; mt < 4; mt++)
#pragma unroll
                for (int nt = 0; nt < 4; nt++)
                    mma3(acc[mt][nt], ah[mt], al[mt], bh[nt], bl[nt]);
        }
        __syncthreads();
    }

#pragma unroll
    for (int mt = 0; mt < 4; mt++) {
#pragma unroll
        for (int nt = 0; nt < 4; nt++) {
            int col = col0 + wn * 32 + nt * 8 + 2 * tg;
            float2 b2 = *(const float2*)&bias[col];
            int r0 = row0 + wm * 64 + mt * 16 + g;
            if (r0 < M) {
                float2 o = { acc[mt][nt][0] * outScale + b2.x, acc[mt][nt][1] * outScale + b2.y };
                *(float2*)&C[(size_t)r0 * N + col] = o;
            }
            int r1 = r0 + 8;
            if (r1 < M) {
                float2 o = { acc[mt][nt][2] * outScale + b2.x, acc[mt][nt][3] * outScale + b2.y };
                *(float2*)&C[(size_t)r1 * N + col] = o;
            }
        }
    }
}

// ---------------------------------------------------------------------------
// Fused RMSNorm + RoPE, emits packed fp16 hi/lo pairs (pairs along dim)
// ---------------------------------------------------------------------------
__global__ void rms_rope_split_kernel(const float* __restrict__ Y,
                                      const float* __restrict__ g,
                                      const float* __restrict__ freqs,
                                      const int* __restrict__ grid_sizes,
                                      uint32_t* __restrict__ ohi, uint32_t* __restrict__ olo,
                                      int L, int dim, int c)
{
    int t = blockIdx.x;
    int tid = threadIdx.x;
    const float* row = Y + (size_t)t * dim;

    float4 v = *reinterpret_cast<const float4*>(&row[4 * tid]);
    float ss = v.x * v.x + v.y * v.y + v.z * v.z + v.w * v.w;

    __shared__ float red[32];
#pragma unroll
    for (int o = 16; o > 0; o >>= 1) ss += __shfl_xor_sync(0xffffffffu, ss, o);
    int warp = tid >> 5, lane = tid & 31;
    int nwarps = blockDim.x >> 5;
    if (lane == 0) red[warp] = ss;
    __syncthreads();
    __shared__ float s_inv;
    if (tid == 0) {
        float tot = 0.f;
        for (int i = 0; i < nwarps; i++) tot += red[i];
        s_inv = rsqrtf(tot / (float)dim + 1e-6f);
    }
    __syncthreads();
    float inv = s_inv;

    float4 gg = *reinterpret_cast<const float4*>(&g[4 * tid]);
    v.x *= inv * gg.x; v.y *= inv * gg.y; v.z *= inv * gg.z; v.w *= inv * gg.w;

    int gf = grid_sizes[0], gh = grid_sizes[1], gw = grid_sizes[2];
    int hw = gh * gw;
    int sl = gf * hw;
    if (t < sl) {
        int fi = t / hw;
        int rem = t - fi * hw;
        int hi2 = rem / gw;
        int wi = rem - hi2 * gw;
        int c1 = c / 3;
        int c0 = c - 2 * c1;
#pragma unroll
        for (int pp = 0; pp < 2; pp++) {
            int p = 2 * tid + pp;
            int j = p % c;
            int idx = (j < c0) ? fi : ((j < c0 + c1) ? hi2 : wi);
            float ang = freqs[(size_t)idx * c + j];
            float sn, cs;
            sincosf(ang, &sn, &cs);
            float re = (pp == 0) ? v.x : v.z;
            float im = (pp == 0) ? v.y : v.w;
            float re2 = re * cs - im * sn;
            float im2 = re * sn + im * cs;
            if (pp == 0) { v.x = re2; v.y = im2; }
            else         { v.z = re2; v.w = im2; }
        }
    }
    size_t pbase = (size_t)t * (dim / 2) + 2 * tid;
    uint32_t h0, l0, h1, l1;
    split2(v.x, v.y, h0, l0);
    split2(v.z, v.w, h1, l1);
    ohi[pbase] = h0; olo[pbase] = l0;
    ohi[pbase + 1] = h1; olo[pbase + 1] = l1;
}

// ---------------------------------------------------------------------------
// Flash attention fp16x3. 64q x 64k tiles, d=128 (64 pairs).
// 256 thr, warps 2x4. S warp tile 32x16 (2x2), PV warp tile 32x32 (2x4).
// K/V double-buffered cp.async. Output written as packed pairs.
// ---------------------------------------------------------------------------
#define A_QP 68    // Q/K smem pair stride (64 data + pad)
#define A_VP 136   // V smem pair stride  (128 data + pad)
#define A_PP 36    // P smem pair stride  (32 data + pad)
#define A_SS 68    // fp32 S stride
__global__ void __launch_bounds__(256, 1)
attn_f16x3_kernel(const uint32_t* __restrict__ Qhi, const uint32_t* __restrict__ Qlo,
                  const uint32_t* __restrict__ Khi, const uint32_t* __restrict__ Klo,
                  const uint32_t* __restrict__ Vhi, const uint32_t* __restrict__ Vlo,
                  uint32_t* __restrict__ Ohi, uint32_t* __restrict__ Olo,
                  const int* __restrict__ seq_lens, int L, int nheads)
{
    const int QTS = 64 * A_QP;     // 4352
    const int VTS = 32 * A_VP;     // 4352
    extern __shared__ uint32_t sh[];
    uint32_t* Qh = sh;                   // QTS
    uint32_t* Ql = Qh + QTS;
    uint32_t* Kh = Ql + QTS;             // 2*QTS
    uint32_t* Kl = Kh + 2 * QTS;
    uint32_t* Vh = Kl + 2 * QTS;         // 2*VTS
    uint32_t* Vl = Vh + 2 * VTS;
    uint32_t* Ph = Vl + 2 * VTS;         // 64*A_PP
    uint32_t* Pl = Ph + 64 * A_PP;
    float*    Ps = (float*)(Pl + 64 * A_PP);   // 64*A_SS
    float*    s_m = Ps + 64 * A_SS;
    float*    s_l = s_m + 64;
    float*    s_c = s_l + 64;

    int hd = blockIdx.y;
    int q0 = blockIdx.x * 64;
    int tid = threadIdx.x, lane = tid & 31, warp = tid >> 5;
    int wm = warp >> 2, wn = warp & 3;
    int g = lane >> 2, tg = lane & 3;
    int seqlen = seq_lens[0]; if (seqlen > L) seqlen = L;
    int vprows = (seqlen + 1) >> 1;
    const float scale = rsqrtf(128.f);
    const int hq = hd * 64;     // pair offset into NPAIR row for Q/K/O
    const int hv = hd * 128;    // column offset into Vp row

    // Q tile (one-shot)
#pragma unroll
    for (int i = 0; i < 4; i++) {
        int idx = tid + i * 256;
        int r = idx >> 4, pc = (idx & 15) << 2;
        int gr = q0 + r; if (gr >= L) gr = L - 1;
        size_t go = (size_t)gr * NPAIR + hq + pc;
        cp16(Qh + r * A_QP + pc, Qhi + go);
        cp16(Ql + r * A_QP + pc, Qlo + go);
    }
    auto issueKV = [&](int k0, int buf) {
#pragma unroll
        for (int i = 0; i < 4; i++) {
            int idx = tid + i * 256;
            int r = idx >> 4, pc = (idx & 15) << 2;
            int gr = k0 + r; if (gr >= seqlen) gr = seqlen - 1;
            size_t go = (size_t)gr * NPAIR + hq + pc;
            cp16(Kh + buf * QTS + r * A_QP + pc, Khi + go);
            cp16(Kl + buf * QTS + r * A_QP + pc, Klo + go);
        }
#pragma unroll
        for (int i = 0; i < 4; i++) {
            int idx = tid + i * 256;
            int r = idx >> 5, pc = (idx & 31) << 2;
            int gpr = (k0 >> 1) + r; if (gpr >= vprows) gpr = vprows - 1;
            size_t go = (size_t)gpr * DIMV + hv + pc;
            cp16(Vh + buf * VTS + r * A_VP + pc, Vhi + go);
            cp16(Vl + buf * VTS + r * A_VP + pc, Vlo + go);
        }
    };
    issueKV(0, 0); CP_COMMIT();

    if (tid < 64) { s_m[tid] = -1e30f; s_l[tid] = 0.f; }

    float acc_o[2][4][4];
#pragma unroll
    for (int mt = 0; mt < 2; mt++)
#pragma unroll
        for (int nt = 0; nt < 4; nt++)
#pragma unroll
            for (int r = 0; r < 4; r++) acc_o[mt][nt][r] = 0.f;

    int nkt = (seqlen + 63) >> 6;
    for (int t = 0; t < nkt; t++) {
        int buf = t & 1;
        if (t + 1 < nkt) { issueKV((t + 1) * 64, buf ^ 1); CP_COMMIT(); CP_WAIT(1); }
        else            { CP_WAIT(0); }
        __syncthreads();

        // ---- S = Q K^T ----
        const uint32_t* Kbh = Kh + buf * QTS;
        const uint32_t* Kbl = Kl + buf * QTS;
        float acc_s[2][2][4];
#pragma unroll
        for (int mt = 0; mt < 2; mt++)
#pragma unroll
            for (int nt = 0; nt < 2; nt++)
#pragma unroll
                for (int r = 0; r < 4; r++) acc_s[mt][nt][r] = 0.f;

#pragma unroll
        for (int ks = 0; ks < 8; ks++) {
            int pb = ks * 8;
            uint32_t ah[2][4], al[2][4], bh[2][2], bl[2][2];
#pragma unroll
            for (int mt = 0; mt < 2; mt++) {
                int r0 = (wm * 32 + mt * 16 + g) * A_QP, r1 = r0 + 8 * A_QP;
                ah[mt][0] = Qh[r0 + pb + tg];     al[mt][0] = Ql[r0 + pb + tg];
                ah[mt][1] = Qh[r1 + pb + tg];     al[mt][1] = Ql[r1 + pb + tg];
                ah[mt][2] = Qh[r0 + pb + tg + 4]; al[mt][2] = Ql[r0 + pb + tg + 4];
                ah[mt][3] = Qh[r1 + pb + tg + 4]; al[mt][3] = Ql[r1 + pb + tg + 4];
            }
#pragma unroll
            for (int nt = 0; nt < 2; nt++) {
                int rr = (wn * 16 + nt * 8 + g) * A_QP;
                bh[nt][0] = Kbh[rr + pb + tg];     bl[nt][0] = Kbl[rr + pb + tg];
                bh[nt][1] = Kbh[rr + pb + tg + 4]; bl[nt][1] = Kbl[rr + pb + tg + 4];
            }
#pragma unroll
            for (int mt = 0; mt < 2; mt++)
#pragma unroll
                for (int nt = 0; nt < 2; nt++)
                    mma3(acc_s[mt][nt], ah[mt], al[mt], bh[nt], bl[nt]);
        }
        // write fp32 S
#pragma unroll
        for (int mt = 0; mt < 2; mt++) {
            int r0 = wm * 32 + mt * 16 + g;
#pragma unroll
            for (int nt = 0; nt < 2; nt++) {
                int cc = wn * 16 + nt * 8 + 2 * tg;
                *(float2*)&Ps[r0 * A_SS + cc]       = make_float2(acc_s[mt][nt][0], acc_s[mt][nt][1]);
                *(float2*)&Ps[(r0 + 8) * A_SS + cc] = make_float2(acc_s[mt][nt][2], acc_s[mt][nt][3]);
            }
        }
        __syncthreads();

        // ---- online softmax: 4 threads per row; emit packed fp16 P ----
        {
            int row = tid >> 2, sub = tid & 3;
            int k0 = t * 64;
            const float* pr = Ps + row * A_SS + sub * 16;
            float vals[16];
            float mx = -1e30f;
#pragma unroll
            for (int j = 0; j < 16; j++) {
                int col = sub * 16 + j;
                float vv = (k0 + col < seqlen) ? pr[j] * scale : -1e30f;
                vals[j] = vv;
                mx = fmaxf(mx, vv);
            }
            mx = fmaxf(mx, __shfl_xor_sync(0xffffffffu, mx, 1));
            mx = fmaxf(mx, __shfl_xor_sync(0xffffffffu, mx, 2));
            float mold = s_m[row];
            float mnew = fmaxf(mold, mx);
            float ls = 0.f;
#pragma unroll
            for (int j = 0; j < 16; j++) {
                vals[j] = __expf(vals[j] - mnew);
                ls += vals[j];
            }
#pragma unroll
            for (int jp = 0; jp < 8; jp++) {
                uint32_t hh, ll;
                split2(vals[2 * jp], vals[2 * jp + 1], hh, ll);
                Ph[row * A_PP + sub * 8 + jp] = hh;
                Pl[row * A_PP + sub * 8 + jp] = ll;
            }
            ls += __shfl_xor_sync(0xffffffffu, ls, 1);
            ls += __shfl_xor_sync(0xffffffffu, ls, 2);
            if (sub == 0) {
                float cf = __expf(mold - mnew);
                s_m[row] = mnew;
                s_l[row] = s_l[row] * cf + ls;
                s_c[row] = cf;
            }
        }
        __syncthreads();

        // ---- rescale + O += P @ V ----
        const uint32_t* Vbh = Vh + buf * VTS;
        const uint32_t* Vbl = Vl + buf * VTS;
#pragma unroll
        for (int mt = 0; mt < 2; mt++) {
            int r0 = wm * 32 + mt * 16 + g;
            float cf0 = s_c[r0], cf1 = s_c[r0 + 8];
#pragma unroll
            for (int nt = 0; nt < 4; nt++) {
                acc_o[mt][nt][0] *= cf0; acc_o[mt][nt][1] *= cf0;
                acc_o[mt][nt][2] *= cf1; acc_o[mt][nt][3] *= cf1;
            }
        }
#pragma unroll
        for (int ks = 0; ks < 4; ks++) {
            int pb = ks * 8;
            uint32_t ah[2][4], al[2][4], bh[4][2], bl[4][2];
#pragma unroll
            for (int mt = 0; mt < 2; mt++) {
                int r0 = (wm * 32 + mt * 16 + g) * A_PP, r1 = r0 + 8 * A_PP;
                ah[mt][0] = Ph[r0 + pb + tg];     al[mt][0] = Pl[r0 + pb + tg];
                ah[mt][1] = Ph[r1 + pb + tg];     al[mt][1] = Pl[r1 + pb + tg];
                ah[mt][2] = Ph[r0 + pb + tg + 4]; al[mt][2] = Pl[r0 + pb + tg + 4];
                ah[mt][3] = Ph[r1 + pb + tg + 4]; al[mt][3] = Pl[r1 + pb + tg + 4];
            }
#pragma unroll
            for (int nt = 0; nt < 4; nt++) {
                int cc = wn * 32 + nt * 8 + g;
                bh[nt][0] = Vbh[(pb + tg) * A_VP + cc];     bl[nt][0] = Vbl[(pb + tg) * A_VP + cc];
                bh[nt][1] = Vbh[(pb + tg + 4) * A_VP + cc]; bl[nt][1] = Vbl[(pb + tg + 4) * A_VP + cc];
            }
#pragma unroll
            for (int mt = 0; mt < 2; mt++)
#pragma unroll
                for (int nt = 0; nt < 4; nt++)
                    mma3(acc_o[mt][nt], ah[mt], al[mt], bh[nt], bl[nt]);
        }
        __syncthreads();
    }

    // ---- epilogue: normalize + store packed pairs ----
#pragma unroll
    for (int mt = 0; mt < 2; mt++) {
        int r0 = wm * 32 + mt * 16 + g;
        float il0 = 1.f / s_l[r0];
        float il1 = 1.f / s_l[r0 + 8];
#pragma unroll
        for (int nt = 0; nt < 4; nt++) {
            int pidx = wn * 16 + nt * 4 + tg;      // pair index within head
            int gr0 = q0 + r0;
            if (gr0 < L) {
                uint32_t hh, ll;
                split2(acc_o[mt][nt][0] * il0, acc_o[mt][nt][1] * il0, hh, ll);
                Ohi[(size_t)gr0 * NPAIR + hq + pidx] = hh;
                Olo[(size_t)gr0 * NPAIR + hq + pidx] = ll;
            }
            int gr1 = gr0 + 8;
            if (gr1 < L) {
                uint32_t hh, ll;
                split2(acc_o[mt][nt][2] * il1, acc_o[mt][nt][3] * il1, hh, ll);
                Ohi[(size_t)gr1 * NPAIR + hq + pidx] = hh;
                Olo[(size_t)gr1 * NPAIR + hq + pidx] = ll;
            }
        }
    }
}

// ---------------------------------------------------------------------------
// Host launcher
// ---------------------------------------------------------------------------
extern "C" void kernel_launch(void* const* d_in, const int* in_sizes, int n_in,
                              void* d_out, int out_size)
{
    const float* x        = (const float*)d_in[0];
    const int*   seq_lens = (const int*)  d_in[1];
    const int*   grid_szs = (const int*)  d_in[2];
    const float* freqs    = (const float*)d_in[3];
    const float* Wq       = (const float*)d_in[4];
    const float* bq       = (const float*)d_in[5];
    const float* Wk       = (const float*)d_in[6];
    const float* bk       = (const float*)d_in[7];
    const float* Wv       = (const float*)d_in[8];
    const float* bv       = (const float*)d_in[9];
    const float* Wo       = (const float*)d_in[10];
    const float* bo       = (const float*)d_in[11];
    const float* gq       = (const float*)d_in[12];
    const float* gk       = (const float*)d_in[13];

    int dim = in_sizes[5];            // 1536
    int L   = in_sizes[0] / dim;      // 5000
    int c   = in_sizes[3] / 1024;     // 64
    int dh  = 2 * c;                  // 128
    int n   = dim / dh;               // 12
    int Kp  = dim / 2;                // 768

    float *Qb, *Kb, *Vb;
    uint32_t *xp, *wp, *qp, *kp, *vp, *op;
    cudaGetSymbolAddress((void**)&Qb, g_Q);
    cudaGetSymbolAddress((void**)&Kb, g_K);
    cudaGetSymbolAddress((void**)&Vb, g_V);
    cudaGetSymbolAddress((void**)&xp, g_Xp);
    cudaGetSymbolAddress((void**)&wp, g_Wp);
    cudaGetSymbolAddress((void**)&qp, g_Qp);
    cudaGetSymbolAddress((void**)&kp, g_Kp);
    cudaGetSymbolAddress((void**)&vp, g_Vp);
    cudaGetSymbolAddress((void**)&op, g_Op);

    const size_t PLANE = (size_t)MAX_L * NPAIR;
    const size_t WSZ   = (size_t)NPAIR * DIMV;
    const size_t VPLN  = (size_t)(MAX_L / 2) * DIMV;
    uint32_t* xp_h = xp;            uint32_t* xp_l = xp + PLANE;
    uint32_t* qp_h = qp;            uint32_t* qp_l = qp + PLANE;
    uint32_t* kp_h = kp;            uint32_t* kp_l = kp + PLANE;
    uint32_t* op_h = op;            uint32_t* op_l = op + PLANE;
    uint32_t* vp_h = vp;            uint32_t* vp_l = vp + VPLN;
    const float WS = 256.f, IWS = 1.f / 256.f;

    size_t gsmem = (size_t)(2 * 128 * G_PA * 2 + 2 * 16 * G_PB * 2) * 4;   // 75776
    size_t asmem = (size_t)(2 * 64 * A_QP + 4 * 64 * A_QP + 4 * 32 * A_VP +
                            2 * 64 * A_PP + 64 * A_SS + 3 * 64) * 4;        // ~210KB
    cudaFuncSetAttribute(gemm_f16x3_kernel, cudaFuncAttributeMaxDynamicSharedMemorySize, (int)gsmem);
    cudaFuncSetAttribute(attn_f16x3_kernel, cudaFuncAttributeMaxDynamicSharedMemorySize, (int)asmem);

    // ---- prep: splits ----
    int npx = L * Kp;
    split_rows_kernel<<<(npx + 255) / 256, 256>>>(x, xp_h, xp_l, npx);
    int npw = Kp * dim;
    split_k_kernel<<<(npw + 255) / 256, 256>>>(Wq, wp + 0 * WSZ, wp + 1 * WSZ, dim, dim, WS);
    split_k_kernel<<<(npw + 255) / 256, 256>>>(Wk, wp + 2 * WSZ, wp + 3 * WSZ, dim, dim, WS);
    split_k_kernel<<<(npw + 255) / 256, 256>>>(Wv, wp + 4 * WSZ, wp + 5 * WSZ, dim, dim, WS);
    split_k_kernel<<<(npw + 255) / 256, 256>>>(Wo, wp + 6 * WSZ, wp + 7 * WSZ, dim, dim, WS);

    // ---- projections ----
    dim3 ggrid((L + 127) / 128, dim / 128);
    gemm_f16x3_kernel<<<ggrid, 256, gsmem>>>(xp_h, xp_l, wp + 0 * WSZ, wp + 1 * WSZ, bq, Qb, L, dim, Kp, IWS);
    gemm_f16x3_kernel<<<ggrid, 256, gsmem>>>(xp_h, xp_l, wp + 2 * WSZ, wp + 3 * WSZ, bk, Kb, L, dim, Kp, IWS);
    gemm_f16x3_kernel<<<ggrid, 256, gsmem>>>(xp_h, xp_l, wp + 4 * WSZ, wp + 5 * WSZ, bv, Vb, L, dim, Kp, IWS);

    // ---- norm + rope -> packed Q/K; split V along tokens ----
    rms_rope_split_kernel<<<L, dim / 4>>>(Qb, gq, freqs, grid_szs, qp_h, qp_l, L, dim, c);
    rms_rope_split_kernel<<<L, dim / 4>>>(Kb, gk, freqs, grid_szs, kp_h, kp_l, L, dim, c);
    int npv = ((L + 1) / 2) * dim;
    split_k_kernel<<<(npv + 255) / 256, 256>>>(Vb, vp_h, vp_l, L, dim, 1.f);

    // ---- attention ----
    attn_f16x3_kernel<<<dim3((L + 63) / 64, n), 256, asmem>>>(
        qp_h, qp_l, kp_h, kp_l, vp_h, vp_l, op_h, op_l, seq_lens, L, n);

    // ---- output projection ----
    gemm_f16x3_kernel<<<ggrid, 256, gsmem>>>(op_h, op_l, wp + 6 * WSZ, wp + 7 * WSZ, bo, (float*)d_out, L, dim, Kp, IWS);
}

// round 9
// speedup vs baseline: 6.2420x; 1.0604x over previous
#include <cuda_runtime.h>
#include <cuda_fp16.h>
#include <math.h>
#include <stdint.h>

// ---------------------------------------------------------------------------
// WanSelfAttention: B=1, L=5000, dim=1536, heads=12, head_dim=128, fp32 I/O.
// R7: fp16x3 error-compensated tensor cores + ldmatrix fragment loads.
// Weights packed TRANSPOSED [N][kpair]; V packed [d][tokenpair] so every
// B-fragment is a non-transposed ldmatrix.x4. Hot loops: LDSM + HMMA only.
// ---------------------------------------------------------------------------

#define MAX_L 5120
#define DIMV  1536
#define NPAIR 768            // DIMV/2
#define VROW  (MAX_L / 2)    // 2560 token-pairs per d row

// fp32 intermediates
__device__ float g_Q[MAX_L * DIMV];
__device__ float g_K[MAX_L * DIMV];
__device__ float g_V[MAX_L * DIMV];
// packed fp16 hi/lo pair buffers
__device__ uint32_t g_Xp[2][MAX_L * NPAIR];        // x: [token][kpair]
__device__ uint32_t g_Wp[8][NPAIR * DIMV];         // W transposed: [n][kpair] x4 weights x(hi,lo)
__device__ uint32_t g_Qp[2][MAX_L * NPAIR];        // [token][dpair]
__device__ uint32_t g_Kp[2][MAX_L * NPAIR];
__device__ uint32_t g_Vp[2][DIMV * VROW];          // V transposed: [d][tokenpair]
__device__ uint32_t g_Op[2][MAX_L * NPAIR];

// ---------------- helpers ----------------
__device__ __forceinline__ void cp16(void* smem_dst, const void* gsrc) {
    uint32_t s = (uint32_t)__cvta_generic_to_shared(smem_dst);
    asm volatile("cp.async.cg.shared.global [%0], [%1], 16;\n" :: "r"(s), "l"(gsrc));
}
#define CP_COMMIT() asm volatile("cp.async.commit_group;\n" ::: "memory")
#define CP_WAIT(n)  asm volatile("cp.async.wait_group %0;\n" :: "n"(n) : "memory")

__device__ __forceinline__ void ldsm4(uint32_t* r, const uint32_t* p) {
    uint32_t a = (uint32_t)__cvta_generic_to_shared(p);
    asm volatile("ldmatrix.sync.aligned.m8n8.x4.shared.b16 {%0,%1,%2,%3}, [%4];"
        : "=r"(r[0]), "=r"(r[1]), "=r"(r[2]), "=r"(r[3]) : "r"(a));
}

// split a pair (x,y) into packed fp16 hi and lo words (x in low half)
__device__ __forceinline__ void split2(float x, float y, uint32_t& hi, uint32_t& lo) {
    __half2 h = __floats2half2_rn(x, y);
    float2 hf = __half22float2(h);
    __half2 l = __floats2half2_rn(x - hf.x, y - hf.y);
    hi = *reinterpret_cast<uint32_t*>(&h);
    lo = *reinterpret_cast<uint32_t*>(&l);
}

__device__ __forceinline__ void mma_f16(float* c, const uint32_t* a, const uint32_t* b) {
    asm volatile(
        "mma.sync.aligned.m16n8k16.row.col.f32.f16.f16.f32 "
        "{%0,%1,%2,%3}, {%4,%5,%6,%7}, {%8,%9}, {%0,%1,%2,%3};\n"
        : "+f"(c[0]), "+f"(c[1]), "+f"(c[2]), "+f"(c[3])
        : "r"(a[0]), "r"(a[1]), "r"(a[2]), "r"(a[3]), "r"(b[0]), "r"(b[1]));
}
__device__ __forceinline__ void mma3(float* c,
                                     const uint32_t* ah, const uint32_t* al,
                                     const uint32_t* bh, const uint32_t* bl) {
    mma_f16(c, al, bh);
    mma_f16(c, ah, bl);
    mma_f16(c, ah, bh);
}

// ---------------------------------------------------------------------------
// Prep: split fp32 rows into packed pairs along the row
// ---------------------------------------------------------------------------
__global__ void split_rows_kernel(const float* __restrict__ X,
                                  uint32_t* __restrict__ hi, uint32_t* __restrict__ lo,
                                  int npairs)
{
    int i = blockIdx.x * 256 + threadIdx.x;
    if (i >= npairs) return;
    float2 v = reinterpret_cast<const float2*>(X)[i];
    uint32_t h, l; split2(v.x, v.y, h, l);
    hi[i] = h; lo[i] = l;
}

// Prep: transposing split. X[R][C] -> out[c][rp] = pack(X[2rp][c], X[2rp+1][c])*scale
// out row stride = RPstride. Tile 64 rows x 32 cols via smem.
__global__ void split_trans_kernel(const float* __restrict__ X,
                                   uint32_t* __restrict__ hi, uint32_t* __restrict__ lo,
                                   int R, int C, int RPstride, float scale)
{
    __shared__ float tile[64][33];
    int r0 = blockIdx.y * 64, c0 = blockIdx.x * 32;
    int tx = threadIdx.x, ty = threadIdx.y;   // 32 x 8
#pragma unroll
    for (int i = 0; i < 8; i++) {
        int r = r0 + ty + i * 8;
        float v = 0.f;
        if (r < R && c0 + tx < C) v = X[(size_t)r * C + c0 + tx] * scale;
        tile[ty + i * 8][tx] = v;
    }
    __syncthreads();
#pragma unroll
    for (int i = 0; i < 4; i++) {
        int cy = ty + i * 8;
        int cc = c0 + cy;
        int rp = (r0 >> 1) + tx;
        if (cc < C && 2 * rp < R) {
            uint32_t h, l;
            split2(tile[2 * tx][cy], tile[2 * tx + 1][cy], h, l);
            hi[(size_t)cc * RPstride + rp] = h;
            lo[(size_t)cc * RPstride + rp] = l;
        }
    }
}

// ---------------------------------------------------------------------------
// GEMM fp16x3: C[M,N] = (Ap @ Bp^T) * outScale + bias
// Ap: [M][Kp] pairs along k.  Bp: [N][Kp] pairs along k (TRANSPOSED weights).
// BM=128 BN=128 BKP=16 pairs (K=32), 256 thr, warps 2x4, warp tile 64x32.
// ---------------------------------------------------------------------------
#define G_ST 20     // smem pair stride for both A and B tiles (16 data + 4 pad)
__global__ void __launch_bounds__(256)
gemm_f16x3_kernel(const uint32_t* __restrict__ Ahi, const uint32_t* __restrict__ Alo,
                  const uint32_t* __restrict__ Bhi, const uint32_t* __restrict__ Blo,
                  const float* __restrict__ bias, float* __restrict__ C,
                  int M, int N, int Kp, float outScale)
{
    const int TBUF = 128 * G_ST;     // 2560 words per tile plane
    extern __shared__ uint32_t sh[];
    uint32_t* Ah = sh;                     // 2*TBUF
    uint32_t* Al = Ah + 2 * TBUF;
    uint32_t* Bh = Al + 2 * TBUF;          // 2*TBUF
    uint32_t* Bl = Bh + 2 * TBUF;

    int tid = threadIdx.x;
    int lane = tid & 31, warp = tid >> 5;
    int wm = warp >> 2, wn = warp & 3;
    int g = lane >> 2, tg = lane & 3;
    int row0 = blockIdx.x * 128, col0 = blockIdx.y * 128;

    // ldmatrix per-thread coordinates
    int arow  = (lane & 7) + ((lane & 8) ? 8 : 0);     // + mt*16 + wm*64
    int apair = (lane & 16) ? 4 : 0;
    int brow  = (lane & 7) + ((lane & 16) ? 8 : 0);    // + nt2*16 + wn*32
    int bpair = (lane & 8) ? 4 : 0;

    float acc[4][4][4];
#pragma unroll
    for (int mt = 0; mt < 4; mt++)
#pragma unroll
        for (int nt = 0; nt < 4; nt++)
#pragma unroll
            for (int r = 0; r < 4; r++) acc[mt][nt][r] = 0.f;

    auto issue = [&](int ktp, int buf) {
#pragma unroll
        for (int i = 0; i < 2; i++) {
            int idx = tid + i * 256;
            int r = idx >> 2, pc = (idx & 3) << 2;
            int gr = row0 + r; if (gr >= M) gr = M - 1;
            size_t go = (size_t)gr * Kp + ktp + pc;
            cp16(Ah + buf * TBUF + r * G_ST + pc, Ahi + go);
            cp16(Al + buf * TBUF + r * G_ST + pc, Alo + go);
        }
#pragma unroll
        for (int i = 0; i < 2; i++) {
            int idx = tid + i * 256;
            int r = idx >> 2, pc = (idx & 3) << 2;
            size_t go = (size_t)(col0 + r) * Kp + ktp + pc;
            cp16(Bh + buf * TBUF + r * G_ST + pc, Bhi + go);
            cp16(Bl + buf * TBUF + r * G_ST + pc, Blo + go);
        }
    };

    issue(0, 0); CP_COMMIT();
    int nk = Kp / 16;
    for (int t = 0; t < nk; t++) {
        int buf = t & 1;
        if (t + 1 < nk) { issue((t + 1) * 16, buf ^ 1); CP_COMMIT(); CP_WAIT(1); }
        else           { CP_WAIT(0); }
        __syncthreads();

        const uint32_t* Abh = Ah + buf * TBUF;
        const uint32_t* Abl = Al + buf * TBUF;
        const uint32_t* Bbh = Bh + buf * TBUF;
        const uint32_t* Bbl = Bl + buf * TBUF;
#pragma unroll
        for (int ks = 0; ks < 2; ks++) {
            int pb = ks * 8;
            uint32_t ah[4][4], al[4][4], bh2[2][4], bl2[2][4];
#pragma unroll
            for (int mt = 0; mt < 4; mt++) {
                int ro = (wm * 64 + mt * 16 + arow) * G_ST + apair + pb;
                ldsm4(ah[mt], Abh + ro);
                ldsm4(al[mt], Abl + ro);
            }
#pragma unroll
            for (int nt2 = 0; nt2 < 2; nt2++) {
                int ro = (wn * 32 + nt2 * 16 + brow) * G_ST + bpair + pb;
                ldsm4(bh2[nt2], Bbh + ro);
                ldsm4(bl2[nt2], Bbl + ro);
            }
#pragma unroll
            for (int mt = 0; mt < 4; mt++)
#pragma unroll
                for (int nt = 0; nt < 4; nt++) {
                    const uint32_t* bhp = &bh2[nt >> 1][(nt & 1) * 2];
                    const uint32_t* blp = &bl2[nt >> 1][(nt & 1) * 2];
                    mma3(acc[mt][nt], ah[mt], al[mt], bhp, blp);
                }
        }
        __syncthreads();
    }

#pragma unroll
    for (int mt = 0; mt < 4; mt++) {
#pragma unroll
        for (int nt = 0; nt < 4; nt++) {
            int col = col0 + wn * 32 + nt * 8 + 2 * tg;
            float2 b2 = *(const float2*)&bias[col];
            int r0 = row0 + wm * 64 + mt * 16 + g;
            if (r0 < M) {
                float2 o = { acc[mt][nt][0] * outScale + b2.x, acc[mt][nt][1] * outScale + b2.y };
                *(float2*)&C[(size_t)r0 * N + col] = o;
            }
            int r1 = r0 + 8;
            if (r1 < M) {
                float2 o = { acc[mt][nt][2] * outScale + b2.x, acc[mt][nt][3] * outScale + b2.y };
                *(float2*)&C[(size_t)r1 * N + col] = o;
            }
        }
    }
}

// ---------------------------------------------------------------------------
// Fused RMSNorm + RoPE, emits packed fp16 hi/lo pairs (pairs along dim)
// ---------------------------------------------------------------------------
__global__ void rms_rope_split_kernel(const float* __restrict__ Y,
                                      const float* __restrict__ g,
                                      const float* __restrict__ freqs,
                                      const int* __restrict__ grid_sizes,
                                      uint32_t* __restrict__ ohi, uint32_t* __restrict__ olo,
                                      int L, int dim, int c)
{
    int t = blockIdx.x;
    int tid = threadIdx.x;
    const float* row = Y + (size_t)t * dim;

    float4 v = *reinterpret_cast<const float4*>(&row[4 * tid]);
    float ss = v.x * v.x + v.y * v.y + v.z * v.z + v.w * v.w;

    __shared__ float red[32];
#pragma unroll
    for (int o = 16; o > 0; o >>= 1) ss += __shfl_xor_sync(0xffffffffu, ss, o);
    int warp = tid >> 5, lane = tid & 31;
    int nwarps = blockDim.x >> 5;
    if (lane == 0) red[warp] = ss;
    __syncthreads();
    __shared__ float s_inv;
    if (tid == 0) {
        float tot = 0.f;
        for (int i = 0; i < nwarps; i++) tot += red[i];
        s_inv = rsqrtf(tot / (float)dim + 1e-6f);
    }
    __syncthreads();
    float inv = s_inv;

    float4 gg = *reinterpret_cast<const float4*>(&g[4 * tid]);
    v.x *= inv * gg.x; v.y *= inv * gg.y; v.z *= inv * gg.z; v.w *= inv * gg.w;

    int gf = grid_sizes[0], gh = grid_sizes[1], gw = grid_sizes[2];
    int hw = gh * gw;
    int sl = gf * hw;
    if (t < sl) {
        int fi = t / hw;
        int rem = t - fi * hw;
        int hi2 = rem / gw;
        int wi = rem - hi2 * gw;
        int c1 = c / 3;
        int c0 = c - 2 * c1;
#pragma unroll
        for (int pp = 0; pp < 2; pp++) {
            int p = 2 * tid + pp;
            int j = p % c;
            int idx = (j < c0) ? fi : ((j < c0 + c1) ? hi2 : wi);
            float ang = freqs[(size_t)idx * c + j];
            float sn, cs;
            sincosf(ang, &sn, &cs);
            float re = (pp == 0) ? v.x : v.z;
            float im = (pp == 0) ? v.y : v.w;
            float re2 = re * cs - im * sn;
            float im2 = re * sn + im * cs;
            if (pp == 0) { v.x = re2; v.y = im2; }
            else         { v.z = re2; v.w = im2; }
        }
    }
    size_t pbase = (size_t)t * (dim / 2) + 2 * tid;
    uint32_t h0, l0, h1, l1;
    split2(v.x, v.y, h0, l0);
    split2(v.z, v.w, h1, l1);
    ohi[pbase] = h0; olo[pbase] = l0;
    ohi[pbase + 1] = h1; olo[pbase + 1] = l1;
}

// ---------------------------------------------------------------------------
// Flash attention fp16x3 + ldmatrix. 64q x 64k tiles, d=128 (64 pairs).
// 256 thr, warps 2x4. S warp tile 32x16 (2x2), PV warp tile 32x32 (2x4).
// Q/K smem [token][dpair]; V smem [d][tokenpair]; P smem [q][tokenpair].
// ---------------------------------------------------------------------------
#define A_QP 68    // Q/K smem pair stride (64 data + pad)
#define A_VT 36    // V smem token-pair stride (32 data + pad)
#define A_PP 36    // P smem pair stride (32 data + pad)
#define A_SS 68    // fp32 S stride
__global__ void __launch_bounds__(256, 1)
attn_f16x3_kernel(const uint32_t* __restrict__ Qhi, const uint32_t* __restrict__ Qlo,
                  const uint32_t* __restrict__ Khi, const uint32_t* __restrict__ Klo,
                  const uint32_t* __restrict__ Vhi, const uint32_t* __restrict__ Vlo,
                  uint32_t* __restrict__ Ohi, uint32_t* __restrict__ Olo,
                  const int* __restrict__ seq_lens, int L, int nheads)
{
    const int QTS = 64 * A_QP;      // 4352
    const int VTS = 128 * A_VT;     // 4608
    extern __shared__ uint32_t sh[];
    uint32_t* Qh = sh;                   // QTS
    uint32_t* Ql = Qh + QTS;
    uint32_t* Kh = Ql + QTS;             // 2*QTS
    uint32_t* Kl = Kh + 2 * QTS;
    uint32_t* Vh = Kl + 2 * QTS;         // 2*VTS
    uint32_t* Vl = Vh + 2 * VTS;
    uint32_t* Ph = Vl + 2 * VTS;         // 64*A_PP
    uint32_t* Pl = Ph + 64 * A_PP;
    float*    Ps = (float*)(Pl + 64 * A_PP);   // 64*A_SS
    float*    s_m = Ps + 64 * A_SS;
    float*    s_l = s_m + 64;
    float*    s_c = s_l + 64;

    int hd = blockIdx.y;
    int q0 = blockIdx.x * 64;
    int tid = threadIdx.x, lane = tid & 31, warp = tid >> 5;
    int wm = warp >> 2, wn = warp & 3;
    int g = lane >> 2, tg = lane & 3;
    int seqlen = seq_lens[0]; if (seqlen > L) seqlen = L;
    const float scale = rsqrtf(128.f);
    const int hq = hd * 64;     // pair offset into NPAIR row for Q/K/O
    const int hv = hd * 128;    // d-row offset into Vp

    // ldmatrix per-thread coordinates
    int marow  = (lane & 7) + ((lane & 8) ? 8 : 0);   // A-type (Q, P)
    int mapair = (lane & 16) ? 4 : 0;
    int nbrow  = (lane & 7) + ((lane & 16) ? 8 : 0);  // B-type (K, V)
    int nbpair = (lane & 8) ? 4 : 0;

    // Q tile (one-shot)
#pragma unroll
    for (int i = 0; i < 4; i++) {
        int idx = tid + i * 256;
        int r = idx >> 4, pc = (idx & 15) << 2;
        int gr = q0 + r; if (gr >= L) gr = L - 1;
        size_t go = (size_t)gr * NPAIR + hq + pc;
        cp16(Qh + r * A_QP + pc, Qhi + go);
        cp16(Ql + r * A_QP + pc, Qlo + go);
    }
    auto issueKV = [&](int k0, int buf) {
#pragma unroll
        for (int i = 0; i < 4; i++) {
            int idx = tid + i * 256;
            int r = idx >> 4, pc = (idx & 15) << 2;
            int gr = k0 + r; if (gr >= seqlen) gr = seqlen - 1;
            size_t go = (size_t)gr * NPAIR + hq + pc;
            cp16(Kh + buf * QTS + r * A_QP + pc, Khi + go);
            cp16(Kl + buf * QTS + r * A_QP + pc, Klo + go);
        }
        int tkp0 = k0 >> 1;
#pragma unroll
        for (int i = 0; i < 4; i++) {
            int idx = tid + i * 256;
            int r = idx >> 3, pc = (idx & 7) << 2;    // r: d row 0..127, pc: 0..28
            size_t go = (size_t)(hv + r) * VROW + tkp0 + pc;
            cp16(Vh + buf * VTS + r * A_VT + pc, Vhi + go);
            cp16(Vl + buf * VTS + r * A_VT + pc, Vlo + go);
        }
    };
    issueKV(0, 0); CP_COMMIT();

    if (tid < 64) { s_m[tid] = -1e30f; s_l[tid] = 0.f; }

    float acc_o[2][4][4];
#pragma unroll
    for (int mt = 0; mt < 2; mt++)
#pragma unroll
        for (int nt = 0; nt < 4; nt++)
#pragma unroll
            for (int r = 0; r < 4; r++) acc_o[mt][nt][r] = 0.f;

    int nkt = (seqlen + 63) >> 6;
    for (int t = 0; t < nkt; t++) {
        int buf = t & 1;
        if (t + 1 < nkt) { issueKV((t + 1) * 64, buf ^ 1); CP_COMMIT(); CP_WAIT(1); }
        else            { CP_WAIT(0); }
        __syncthreads();

        // ---- S = Q K^T ----
        const uint32_t* Kbh = Kh + buf * QTS;
        const uint32_t* Kbl = Kl + buf * QTS;
        float acc_s[2][2][4];
#pragma unroll
        for (int mt = 0; mt < 2; mt++)
#pragma unroll
            for (int nt = 0; nt < 2; nt++)
#pragma unroll
                for (int r = 0; r < 4; r++) acc_s[mt][nt][r] = 0.f;

#pragma unroll
        for (int ks = 0; ks < 8; ks++) {
            int pb = ks * 8;
            uint32_t ah[2][4], al[2][4], bh2[4], bl2[4];
#pragma unroll
            for (int mt = 0; mt < 2; mt++) {
                int ro = (wm * 32 + mt * 16 + marow) * A_QP + mapair + pb;
                ldsm4(ah[mt], Qh + ro);
                ldsm4(al[mt], Ql + ro);
            }
            {
                int ro = (wn * 16 + nbrow) * A_QP + nbpair + pb;
                ldsm4(bh2, Kbh + ro);
                ldsm4(bl2, Kbl + ro);
            }
#pragma unroll
            for (int mt = 0; mt < 2; mt++)
#pragma unroll
                for (int nt = 0; nt < 2; nt++)
                    mma3(acc_s[mt][nt], ah[mt], al[mt], &bh2[nt * 2], &bl2[nt * 2]);
        }
        // write fp32 S
#pragma unroll
        for (int mt = 0; mt < 2; mt++) {
            int r0 = wm * 32 + mt * 16 + g;
#pragma unroll
            for (int nt = 0; nt < 2; nt++) {
                int cc = wn * 16 + nt * 8 + 2 * tg;
                *(float2*)&Ps[r0 * A_SS + cc]       = make_float2(acc_s[mt][nt][0], acc_s[mt][nt][1]);
                *(float2*)&Ps[(r0 + 8) * A_SS + cc] = make_float2(acc_s[mt][nt][2], acc_s[mt][nt][3]);
            }
        }
        __syncthreads();

        // ---- online softmax: 4 threads per row; emit packed fp16 P ----
        {
            int row = tid >> 2, sub = tid & 3;
            int k0 = t * 64;
            const float* pr = Ps + row * A_SS + sub * 16;
            float vals[16];
            float mx = -1e30f;
#pragma unroll
            for (int j = 0; j < 16; j++) {
                int col = sub * 16 + j;
                float vv = (k0 + col < seqlen) ? pr[j] * scale : -1e30f;
                vals[j] = vv;
                mx = fmaxf(mx, vv);
            }
            mx = fmaxf(mx, __shfl_xor_sync(0xffffffffu, mx, 1));
            mx = fmaxf(mx, __shfl_xor_sync(0xffffffffu, mx, 2));
            float mold = s_m[row];
            float mnew = fmaxf(mold, mx);
            float ls = 0.f;
#pragma unroll
            for (int j = 0; j < 16; j++) {
                vals[j] = __expf(vals[j] - mnew);
                ls += vals[j];
            }
#pragma unroll
            for (int jp = 0; jp < 8; jp++) {
                uint32_t hh, ll;
                split2(vals[2 * jp], vals[2 * jp + 1], hh, ll);
                Ph[row * A_PP + sub * 8 + jp] = hh;
                Pl[row * A_PP + sub * 8 + jp] = ll;
            }
            ls += __shfl_xor_sync(0xffffffffu, ls, 1);
            ls += __shfl_xor_sync(0xffffffffu, ls, 2);
            if (sub == 0) {
                float cf = __expf(mold - mnew);
                s_m[row] = mnew;
                s_l[row] = s_l[row] * cf + ls;
                s_c[row] = cf;
            }
        }
        __syncthreads();

        // ---- rescale + O += P @ V ----
        const uint32_t* Vbh = Vh + buf * VTS;
        const uint32_t* Vbl = Vl + buf * VTS;
#pragma unroll
        for (int mt = 0; mt < 2; mt++) {
            int r0 = wm * 32 + mt * 16 + g;
            float cf0 = s_c[r0], cf1 = s_c[r0 + 8];
#pragma unroll
            for (int nt = 0; nt < 4; nt++) {
                acc_o[mt][nt][0] *= cf0; acc_o[mt][nt][1] *= cf0;
                acc_o[mt][nt][2] *= cf1; acc_o[mt][nt][3] *= cf1;
            }
        }
#pragma unroll
        for (int ks = 0; ks < 4; ks++) {
            int pb = ks * 8;
            uint32_t ah[2][4], al[2][4], bh2[2][4], bl2[2][4];
#pragma unroll
            for (int mt = 0; mt < 2; mt++) {
                int ro = (wm * 32 + mt * 16 + marow) * A_PP + mapair + pb;
                ldsm4(ah[mt], Ph + ro);
                ldsm4(al[mt], Pl + ro);
            }
#pragma unroll
            for (int nt2 = 0; nt2 < 2; nt2++) {
                int ro = (wn * 32 + nt2 * 16 + nbrow) * A_VT + nbpair + pb;
                ldsm4(bh2[nt2], Vbh + ro);
                ldsm4(bl2[nt2], Vbl + ro);
            }
#pragma unroll
            for (int mt = 0; mt < 2; mt++)
#pragma unroll
                for (int nt = 0; nt < 4; nt++) {
                    const uint32_t* bhp = &bh2[nt >> 1][(nt & 1) * 2];
                    const uint32_t* blp = &bl2[nt >> 1][(nt & 1) * 2];
                    mma3(acc_o[mt][nt], ah[mt], al[mt], bhp, blp);
                }
        }
        __syncthreads();
    }

    // ---- epilogue: normalize + store packed pairs ----
#pragma unroll
    for (int mt = 0; mt < 2; mt++) {
        int r0 = wm * 32 + mt * 16 + g;
        float il0 = 1.f / s_l[r0];
        float il1 = 1.f / s_l[r0 + 8];
#pragma unroll
        for (int nt = 0; nt < 4; nt++) {
            int pidx = wn * 16 + nt * 4 + tg;      // pair index within head
            int gr0 = q0 + r0;
            if (gr0 < L) {
                uint32_t hh, ll;
                split2(acc_o[mt][nt][0] * il0, acc_o[mt][nt][1] * il0, hh, ll);
                Ohi[(size_t)gr0 * NPAIR + hq + pidx] = hh;
                Olo[(size_t)gr0 * NPAIR + hq + pidx] = ll;
            }
            int gr1 = gr0 + 8;
            if (gr1 < L) {
                uint32_t hh, ll;
                split2(acc_o[mt][nt][2] * il1, acc_o[mt][nt][3] * il1, hh, ll);
                Ohi[(size_t)gr1 * NPAIR + hq + pidx] = hh;
                Olo[(size_t)gr1 * NPAIR + hq + pidx] = ll;
            }
        }
    }
}

// ---------------------------------------------------------------------------
// Host launcher
// ---------------------------------------------------------------------------
extern "C" void kernel_launch(void* const* d_in, const int* in_sizes, int n_in,
                              void* d_out, int out_size)
{
    const float* x        = (const float*)d_in[0];
    const int*   seq_lens = (const int*)  d_in[1];
    const int*   grid_szs = (const int*)  d_in[2];
    const float* freqs    = (const float*)d_in[3];
    const float* Wq       = (const float*)d_in[4];
    const float* bq       = (const float*)d_in[5];
    const float* Wk       = (const float*)d_in[6];
    const float* bk       = (const float*)d_in[7];
    const float* Wv       = (const float*)d_in[8];
    const float* bv       = (const float*)d_in[9];
    const float* Wo       = (const float*)d_in[10];
    const float* bo       = (const float*)d_in[11];
    const float* gq       = (const float*)d_in[12];
    const float* gk       = (const float*)d_in[13];

    int dim = in_sizes[5];            // 1536
    int L   = in_sizes[0] / dim;      // 5000
    int c   = in_sizes[3] / 1024;     // 64
    int dh  = 2 * c;                  // 128
    int n   = dim / dh;               // 12
    int Kp  = dim / 2;                // 768

    float *Qb, *Kb, *Vb;
    uint32_t *xp, *wp, *qp, *kp, *vp, *op;
    cudaGetSymbolAddress((void**)&Qb, g_Q);
    cudaGetSymbolAddress((void**)&Kb, g_K);
    cudaGetSymbolAddress((void**)&Vb, g_V);
    cudaGetSymbolAddress((void**)&xp, g_Xp);
    cudaGetSymbolAddress((void**)&wp, g_Wp);
    cudaGetSymbolAddress((void**)&qp, g_Qp);
    cudaGetSymbolAddress((void**)&kp, g_Kp);
    cudaGetSymbolAddress((void**)&vp, g_Vp);
    cudaGetSymbolAddress((void**)&op, g_Op);

    const size_t PLANE = (size_t)MAX_L * NPAIR;
    const size_t WSZ   = (size_t)NPAIR * DIMV;
    const size_t VPLN  = (size_t)DIMV * VROW;
    uint32_t* xp_h = xp;            uint32_t* xp_l = xp + PLANE;
    uint32_t* qp_h = qp;            uint32_t* qp_l = qp + PLANE;
    uint32_t* kp_h = kp;            uint32_t* kp_l = kp + PLANE;
    uint32_t* op_h = op;            uint32_t* op_l = op + PLANE;
    uint32_t* vp_h = vp;            uint32_t* vp_l = vp + VPLN;
    const float WS = 256.f, IWS = 1.f / 256.f;

    size_t gsmem = (size_t)(4 * 2 * 128 * G_ST) * 4;                          // 81920
    size_t asmem = (size_t)(2 * 64 * A_QP + 4 * 64 * A_QP + 4 * 128 * A_VT +
                            2 * 64 * A_PP + 64 * A_SS + 3 * 64) * 4;          // 214784
    cudaFuncSetAttribute(gemm_f16x3_kernel, cudaFuncAttributeMaxDynamicSharedMemorySize, (int)gsmem);
    cudaFuncSetAttribute(attn_f16x3_kernel, cudaFuncAttributeMaxDynamicSharedMemorySize, (int)asmem);

    // ---- prep: splits ----
    int npx = L * Kp;
    split_rows_kernel<<<(npx + 255) / 256, 256>>>(x, xp_h, xp_l, npx);
    {
        dim3 tg(32, 8), tgr(dim / 32, (dim + 63) / 64);
        split_trans_kernel<<<tgr, tg>>>(Wq, wp + 0 * WSZ, wp + 1 * WSZ, dim, dim, Kp, WS);
        split_trans_kernel<<<tgr, tg>>>(Wk, wp + 2 * WSZ, wp + 3 * WSZ, dim, dim, Kp, WS);
        split_trans_kernel<<<tgr, tg>>>(Wv, wp + 4 * WSZ, wp + 5 * WSZ, dim, dim, Kp, WS);
        split_trans_kernel<<<tgr, tg>>>(Wo, wp + 6 * WSZ, wp + 7 * WSZ, dim, dim, Kp, WS);
    }

    // ---- projections ----
    dim3 ggrid((L + 127) / 128, dim / 128);
    gemm_f16x3_kernel<<<ggrid, 256, gsmem>>>(xp_h, xp_l, wp + 0 * WSZ, wp + 1 * WSZ, bq, Qb, L, dim, Kp, IWS);
    gemm_f16x3_kernel<<<ggrid, 256, gsmem>>>(xp_h, xp_l, wp + 2 * WSZ, wp + 3 * WSZ, bk, Kb, L, dim, Kp, IWS);
    gemm_f16x3_kernel<<<ggrid, 256, gsmem>>>(xp_h, xp_l, wp + 4 * WSZ, wp + 5 * WSZ, bv, Vb, L, dim, Kp, IWS);

    // ---- norm + rope -> packed Q/K; transpose-split V ----
    rms_rope_split_kernel<<<L, dim / 4>>>(Qb, gq, freqs, grid_szs, qp_h, qp_l, L, dim, c);
    rms_rope_split_kernel<<<L, dim / 4>>>(Kb, gk, freqs, grid_szs, kp_h, kp_l, L, dim, c);
    {
        dim3 tg(32, 8), tgr(dim / 32, (L + 63) / 64);
        split_trans_kernel<<<tgr, tg>>>(Vb, vp_h, vp_l, L, dim, VROW, 1.f);
    }

    // ---- attention ----
    attn_f16x3_kernel<<<dim3((L + 63) / 64, n), 256, asmem>>>(
        qp_h, qp_l, kp_h, kp_l, vp_h, vp_l, op_h, op_l, seq_lens, L, n);

    // ---- output projection ----
    gemm_f16x3_kernel<<<ggrid, 256, gsmem>>>(op_h, op_l, wp + 6 * WSZ, wp + 7 * WSZ, bo, (float*)d_out, L, dim, Kp, IWS);
}